// round 1
// baseline (speedup 1.0000x reference)
#include <cuda_runtime.h>
#include <math.h>

// Problem constants
#define NB 8          // batch
#define SQ 1024       // query seq
#define SK 1024       // key seq
#define DD 1024       // model dim
#define NH 8          // heads
#define DH 128        // head dim
#define HB (NH*NB)    // 64 head*batch
#define XSIZE (NB*SQ*DD)        // 8388608 floats  (x output)
#define NEGV (-4294967295.0f)   // -2^32+1
#define SCALE 0.0883883476483184405f  // 1/sqrt(128)

// Scratch (device globals — no allocation allowed)
__device__ float g_K[HB*SK*DH];   // [(h*NB+b)*SK + s][DH]
__device__ float g_V[HB*SK*DH];
__device__ float g_Q[HB*SQ*DH];
__device__ float g_O[NB*SQ*DD];   // attn output, [b][q][h*DH+d]
__device__ float g_X[NB*SQ*DD];   // pre-LN
__device__ int   g_maskmode;      // 0=int32, 1=float32, 2=uint8

// ---------------------------------------------------------------------------
// Mask dtype detection (deterministic, content-based)
// ---------------------------------------------------------------------------
__global__ void detect_mask_kernel(const void* __restrict__ mask) {
    int t = threadIdx.x;  // 32 threads
    const int*   pi = (const int*)mask;
    const float* pf = (const float*)mask;
    bool oki = true, okf = true;
    for (int i = t; i < 256; i += 32) {
        int v = pi[i];
        oki = oki && (v == 0 || v == 1);
        float f = pf[i];
        okf = okf && (f == 0.0f || f == 1.0f);
    }
    oki = __all_sync(0xFFFFFFFFu, oki);
    okf = __all_sync(0xFFFFFFFFu, okf);
    if (t == 0) g_maskmode = oki ? 0 : (okf ? 1 : 2);
}

// ---------------------------------------------------------------------------
// Projection GEMM: P = A(8192x1024) @ W(1024x1024), z selects (K,V,Q).
// Writes head-split: Out[((h*NB+b)*S + s)*128 + d]
// ---------------------------------------------------------------------------
__global__ __launch_bounds__(256) void proj_kernel(
    const float* __restrict__ mem, const float* __restrict__ dec,
    const float* __restrict__ Wk, const float* __restrict__ Wv,
    const float* __restrict__ Wq)
{
    const int which = blockIdx.z;
    const float* A = (which == 2) ? dec : mem;
    const float* W = (which == 0) ? Wk : ((which == 1) ? Wv : Wq);
    float* Out = (which == 0) ? g_K : ((which == 1) ? g_V : g_Q);

    __shared__ float As[8][128];
    __shared__ float Bs[8][128];

    const int tid = threadIdx.x;
    const int tx = tid & 15, ty = tid >> 4;
    const int bx = blockIdx.x, by = blockIdx.y;

    const int arow  = tid >> 1;
    const int acol4 = (tid & 1) << 2;
    const int brow  = tid >> 5;
    const int bcol4 = (tid & 31) << 2;

    const float* Aptr = A + (by*128 + arow)*1024 + acol4;
    const float* Bptr = W + brow*1024 + bx*128 + bcol4;

    float acc[8][8];
    #pragma unroll
    for (int i = 0; i < 8; i++)
        #pragma unroll
        for (int j = 0; j < 8; j++) acc[i][j] = 0.f;

    for (int k0 = 0; k0 < 1024; k0 += 8) {
        float4 av = *(const float4*)(Aptr + k0);
        float4 bv = *(const float4*)(Bptr + k0*1024);
        __syncthreads();
        As[acol4+0][arow] = av.x;
        As[acol4+1][arow] = av.y;
        As[acol4+2][arow] = av.z;
        As[acol4+3][arow] = av.w;
        *(float4*)&Bs[brow][bcol4] = bv;
        __syncthreads();
        #pragma unroll
        for (int kk = 0; kk < 8; kk++) {
            float a[8], b[8];
            *(float4*)&a[0] = *(const float4*)&As[kk][ty*8];
            *(float4*)&a[4] = *(const float4*)&As[kk][ty*8+4];
            *(float4*)&b[0] = *(const float4*)&Bs[kk][tx*8];
            *(float4*)&b[4] = *(const float4*)&Bs[kk][tx*8+4];
            #pragma unroll
            for (int i = 0; i < 8; i++)
                #pragma unroll
                for (int j = 0; j < 8; j++)
                    acc[i][j] += a[i]*b[j];
        }
    }
    // h = bx (128-aligned col tile), d = tx*8 + j
    #pragma unroll
    for (int i = 0; i < 8; i++) {
        int row = by*128 + ty*8 + i;
        int bb = row >> 10;
        int ss = row & 1023;
        float* optr = Out + (((bx<<3) + bb)*1024 + ss)*128 + tx*8;
        *(float4*)optr       = make_float4(acc[i][0], acc[i][1], acc[i][2], acc[i][3]);
        *(float4*)(optr + 4) = make_float4(acc[i][4], acc[i][5], acc[i][6], acc[i][7]);
    }
}

// ---------------------------------------------------------------------------
// Scores GEMM (NT): S[hb][q][s] = scale * sum_d Q[q][d]*K[s][d]
// Writes raw scaled scores directly into the attns output region.
// ---------------------------------------------------------------------------
__global__ __launch_bounds__(256) void scores_kernel(float* __restrict__ attn)
{
    const int hb = blockIdx.z;
    const float* Qp = g_Q + hb*SQ*DH;
    const float* Kp = g_K + hb*SK*DH;

    __shared__ float As[8][128];
    __shared__ float Bs[8][128];
    const int tid = threadIdx.x;
    const int tx = tid & 15, ty = tid >> 4;
    const int bx = blockIdx.x, by = blockIdx.y;

    const int arow  = tid >> 1;
    const int acol4 = (tid & 1) << 2;

    const float* Aptr = Qp + (by*128 + arow)*128 + acol4;
    const float* Bptr = Kp + (bx*128 + arow)*128 + acol4;

    float acc[8][8];
    #pragma unroll
    for (int i = 0; i < 8; i++)
        #pragma unroll
        for (int j = 0; j < 8; j++) acc[i][j] = 0.f;

    for (int k0 = 0; k0 < 128; k0 += 8) {
        float4 av = *(const float4*)(Aptr + k0);
        float4 bv = *(const float4*)(Bptr + k0);
        __syncthreads();
        As[acol4+0][arow] = av.x;
        As[acol4+1][arow] = av.y;
        As[acol4+2][arow] = av.z;
        As[acol4+3][arow] = av.w;
        Bs[acol4+0][arow] = bv.x;
        Bs[acol4+1][arow] = bv.y;
        Bs[acol4+2][arow] = bv.z;
        Bs[acol4+3][arow] = bv.w;
        __syncthreads();
        #pragma unroll
        for (int kk = 0; kk < 8; kk++) {
            float a[8], b[8];
            *(float4*)&a[0] = *(const float4*)&As[kk][ty*8];
            *(float4*)&a[4] = *(const float4*)&As[kk][ty*8+4];
            *(float4*)&b[0] = *(const float4*)&Bs[kk][tx*8];
            *(float4*)&b[4] = *(const float4*)&Bs[kk][tx*8+4];
            #pragma unroll
            for (int i = 0; i < 8; i++)
                #pragma unroll
                for (int j = 0; j < 8; j++)
                    acc[i][j] += a[i]*b[j];
        }
    }
    #pragma unroll
    for (int i = 0; i < 8; i++) {
        int row = by*128 + ty*8 + i;
        float* optr = attn + ((size_t)hb*SQ + row)*SK + bx*128 + tx*8;
        *(float4*)optr       = make_float4(acc[i][0]*SCALE, acc[i][1]*SCALE,
                                           acc[i][2]*SCALE, acc[i][3]*SCALE);
        *(float4*)(optr + 4) = make_float4(acc[i][4]*SCALE, acc[i][5]*SCALE,
                                           acc[i][6]*SCALE, acc[i][7]*SCALE);
    }
}

// ---------------------------------------------------------------------------
// Masked softmax * query_mask, in place on the attns region.
// One block per (hb, q) row of 1024.
// ---------------------------------------------------------------------------
__global__ __launch_bounds__(256) void softmax_kernel(
    float* __restrict__ attn, const float* __restrict__ qmask,
    const void* __restrict__ mask)
{
    const int rowid = blockIdx.x;     // hb*SQ + q
    const int hb = rowid >> 10;
    const int q  = rowid & 1023;
    const int b  = hb & 7;
    const int tid = threadIdx.x;

    float* rp = attn + (size_t)rowid * SK;
    const int mode = g_maskmode;
    const size_t moff = ((size_t)b*SQ + q)*SK + (size_t)tid*4;

    float4 x = *(const float4*)(rp + tid*4);
    int m0, m1, m2, m3;
    if (mode == 0) {
        int4 mv = *(const int4*)((const int*)mask + moff);
        m0 = mv.x; m1 = mv.y; m2 = mv.z; m3 = mv.w;
    } else if (mode == 1) {
        float4 mv = *(const float4*)((const float*)mask + moff);
        m0 = (mv.x != 0.f); m1 = (mv.y != 0.f); m2 = (mv.z != 0.f); m3 = (mv.w != 0.f);
    } else {
        uchar4 mv = *(const uchar4*)((const unsigned char*)mask + moff);
        m0 = mv.x; m1 = mv.y; m2 = mv.z; m3 = mv.w;
    }
    float v0 = m0 ? NEGV : x.x;
    float v1 = m1 ? NEGV : x.y;
    float v2 = m2 ? NEGV : x.z;
    float v3 = m3 ? NEGV : x.w;

    __shared__ float red[256];
    float mx = fmaxf(fmaxf(v0, v1), fmaxf(v2, v3));
    red[tid] = mx;
    __syncthreads();
    #pragma unroll
    for (int s = 128; s > 0; s >>= 1) {
        if (tid < s) red[tid] = fmaxf(red[tid], red[tid + s]);
        __syncthreads();
    }
    float rowmax = red[0];
    __syncthreads();

    float e0 = expf(v0 - rowmax);
    float e1 = expf(v1 - rowmax);
    float e2 = expf(v2 - rowmax);
    float e3 = expf(v3 - rowmax);
    red[tid] = e0 + e1 + e2 + e3;
    __syncthreads();
    #pragma unroll
    for (int s = 128; s > 0; s >>= 1) {
        if (tid < s) red[tid] += red[tid + s];
        __syncthreads();
    }
    float total = red[0];

    float qm = qmask[b*SQ + q];
    float inv = qm / total;
    *(float4*)(rp + tid*4) = make_float4(e0*inv, e1*inv, e2*inv, e3*inv);
}

// ---------------------------------------------------------------------------
// PV GEMM: O[hb][q][d] = sum_k P[hb][q][k] * V[hb][k][d]
// N = 128 (full head dim per tile). Writes head-concat layout into g_O.
// ---------------------------------------------------------------------------
__global__ __launch_bounds__(256) void pv_kernel(const float* __restrict__ attn)
{
    const int hb = blockIdx.z;
    const float* Ap = attn + (size_t)hb*SQ*SK;
    const float* Vp = g_V + hb*SK*DH;

    __shared__ float As[8][128];
    __shared__ float Bs[8][128];
    const int tid = threadIdx.x;
    const int tx = tid & 15, ty = tid >> 4;
    const int by = blockIdx.y;

    const int arow  = tid >> 1;
    const int acol4 = (tid & 1) << 2;
    const int brow  = tid >> 5;
    const int bcol4 = (tid & 31) << 2;

    const float* Aptr = Ap + (size_t)(by*128 + arow)*1024 + acol4;
    const float* Bptr = Vp + brow*128 + bcol4;

    float acc[8][8];
    #pragma unroll
    for (int i = 0; i < 8; i++)
        #pragma unroll
        for (int j = 0; j < 8; j++) acc[i][j] = 0.f;

    for (int k0 = 0; k0 < 1024; k0 += 8) {
        float4 av = *(const float4*)(Aptr + k0);
        float4 bv = *(const float4*)(Bptr + k0*128);
        __syncthreads();
        As[acol4+0][arow] = av.x;
        As[acol4+1][arow] = av.y;
        As[acol4+2][arow] = av.z;
        As[acol4+3][arow] = av.w;
        *(float4*)&Bs[brow][bcol4] = bv;
        __syncthreads();
        #pragma unroll
        for (int kk = 0; kk < 8; kk++) {
            float a[8], b[8];
            *(float4*)&a[0] = *(const float4*)&As[kk][ty*8];
            *(float4*)&a[4] = *(const float4*)&As[kk][ty*8+4];
            *(float4*)&b[0] = *(const float4*)&Bs[kk][tx*8];
            *(float4*)&b[4] = *(const float4*)&Bs[kk][tx*8+4];
            #pragma unroll
            for (int i = 0; i < 8; i++)
                #pragma unroll
                for (int j = 0; j < 8; j++)
                    acc[i][j] += a[i]*b[j];
        }
    }
    const int b = hb & 7, h = hb >> 3;
    #pragma unroll
    for (int i = 0; i < 8; i++) {
        int q = by*128 + ty*8 + i;
        float* optr = g_O + (b*SQ + q)*DD + h*128 + tx*8;
        *(float4*)optr       = make_float4(acc[i][0], acc[i][1], acc[i][2], acc[i][3]);
        *(float4*)(optr + 4) = make_float4(acc[i][4], acc[i][5], acc[i][6], acc[i][7]);
    }
}

// ---------------------------------------------------------------------------
// Final GEMM: X = [dec | O] @ Wf + bf + dec   (K = 2048, virtual concat)
// ---------------------------------------------------------------------------
__global__ __launch_bounds__(256) void final_kernel(
    const float* __restrict__ dec, const float* __restrict__ Wf,
    const float* __restrict__ bf)
{
    __shared__ float As[8][128];
    __shared__ float Bs[8][128];
    const int tid = threadIdx.x;
    const int tx = tid & 15, ty = tid >> 4;
    const int bx = blockIdx.x, by = blockIdx.y;

    const int arow  = tid >> 1;
    const int acol4 = (tid & 1) << 2;
    const int brow  = tid >> 5;
    const int bcol4 = (tid & 31) << 2;

    const int arow_g = by*128 + arow;

    float acc[8][8];
    #pragma unroll
    for (int i = 0; i < 8; i++)
        #pragma unroll
        for (int j = 0; j < 8; j++) acc[i][j] = 0.f;

    for (int k0 = 0; k0 < 2048; k0 += 8) {
        const float* Asrc = (k0 < 1024) ? (dec + arow_g*1024 + k0)
                                        : (g_O + arow_g*1024 + (k0 - 1024));
        float4 av = *(const float4*)(Asrc + acol4);
        float4 bv = *(const float4*)(Wf + (k0 + brow)*1024 + bx*128 + bcol4);
        __syncthreads();
        As[acol4+0][arow] = av.x;
        As[acol4+1][arow] = av.y;
        As[acol4+2][arow] = av.z;
        As[acol4+3][arow] = av.w;
        *(float4*)&Bs[brow][bcol4] = bv;
        __syncthreads();
        #pragma unroll
        for (int kk = 0; kk < 8; kk++) {
            float a[8], b[8];
            *(float4*)&a[0] = *(const float4*)&As[kk][ty*8];
            *(float4*)&a[4] = *(const float4*)&As[kk][ty*8+4];
            *(float4*)&b[0] = *(const float4*)&Bs[kk][tx*8];
            *(float4*)&b[4] = *(const float4*)&Bs[kk][tx*8+4];
            #pragma unroll
            for (int i = 0; i < 8; i++)
                #pragma unroll
                for (int j = 0; j < 8; j++)
                    acc[i][j] += a[i]*b[j];
        }
    }
    const int c0 = bx*128 + tx*8;
    float4 bf0 = *(const float4*)(bf + c0);
    float4 bf1 = *(const float4*)(bf + c0 + 4);
    #pragma unroll
    for (int i = 0; i < 8; i++) {
        int r = by*128 + ty*8 + i;
        const float* dptr = dec + r*1024 + c0;
        float4 d0 = *(const float4*)dptr;
        float4 d1 = *(const float4*)(dptr + 4);
        float* optr = g_X + r*1024 + c0;
        *(float4*)optr = make_float4(acc[i][0] + bf0.x + d0.x,
                                     acc[i][1] + bf0.y + d0.y,
                                     acc[i][2] + bf0.z + d0.z,
                                     acc[i][3] + bf0.w + d0.w);
        *(float4*)(optr + 4) = make_float4(acc[i][4] + bf1.x + d1.x,
                                           acc[i][5] + bf1.y + d1.y,
                                           acc[i][6] + bf1.z + d1.z,
                                           acc[i][7] + bf1.w + d1.w);
    }
}

// ---------------------------------------------------------------------------
// LayerNorm: one block per row of 1024
// ---------------------------------------------------------------------------
__global__ __launch_bounds__(256) void ln_kernel(
    const float* __restrict__ gamma, const float* __restrict__ beta,
    float* __restrict__ out)
{
    const int rowid = blockIdx.x;
    const int tid = threadIdx.x;
    const float* rp = g_X + (size_t)rowid*1024;

    float4 x = *(const float4*)(rp + tid*4);
    __shared__ float red[256];
    red[tid] = x.x + x.y + x.z + x.w;
    __syncthreads();
    #pragma unroll
    for (int s = 128; s > 0; s >>= 1) {
        if (tid < s) red[tid] += red[tid + s];
        __syncthreads();
    }
    float mean = red[0] * (1.0f / 1024.0f);
    __syncthreads();

    float d0 = x.x - mean, d1 = x.y - mean, d2 = x.z - mean, d3 = x.w - mean;
    red[tid] = d0*d0 + d1*d1 + d2*d2 + d3*d3;
    __syncthreads();
    #pragma unroll
    for (int s = 128; s > 0; s >>= 1) {
        if (tid < s) red[tid] += red[tid + s];
        __syncthreads();
    }
    float var = red[0] * (1.0f / 1024.0f);
    float inv = rsqrtf(var + 1e-5f);

    float4 g  = *(const float4*)(gamma + tid*4);
    float4 bt = *(const float4*)(beta + tid*4);
    float* optr = out + (size_t)rowid*1024 + tid*4;
    *(float4*)optr = make_float4(d0*inv*g.x + bt.x,
                                 d1*inv*g.y + bt.y,
                                 d2*inv*g.z + bt.z,
                                 d3*inv*g.w + bt.w);
}

// ---------------------------------------------------------------------------
extern "C" void kernel_launch(void* const* d_in, const int* in_sizes, int n_in,
                              void* d_out, int out_size) {
    (void)in_sizes; (void)n_in; (void)out_size;
    const float* mem   = (const float*)d_in[0];
    const float* dec   = (const float*)d_in[1];
    const float* qmask = (const float*)d_in[2];
    const float* Wk    = (const float*)d_in[3];
    const float* Wv    = (const float*)d_in[4];
    const float* Wq    = (const float*)d_in[5];
    const float* Wf    = (const float*)d_in[6];
    const float* bf    = (const float*)d_in[7];
    const float* gamma = (const float*)d_in[8];
    const float* beta  = (const float*)d_in[9];
    const void*  mask  = d_in[10];

    float* out  = (float*)d_out;
    float* attn = out + XSIZE;   // attns region follows x

    detect_mask_kernel<<<1, 32>>>(mask);
    proj_kernel<<<dim3(8, 64, 3), 256>>>(mem, dec, Wk, Wv, Wq);
    scores_kernel<<<dim3(8, 8, 64), 256>>>(attn);
    softmax_kernel<<<65536, 256>>>(attn, qmask, mask);
    pv_kernel<<<dim3(1, 8, 64), 256>>>(attn);
    final_kernel<<<dim3(8, 64), 256>>>(dec, Wf, bf);
    ln_kernel<<<8192, 256>>>(gamma, beta, out);
}

// round 6
// speedup vs baseline: 2.0937x; 2.0937x over previous
#include <cuda_runtime.h>
#include <cuda_bf16.h>
#include <cstdint>
#include <math.h>

// ---------------------------------------------------------------------------
// Problem constants
// ---------------------------------------------------------------------------
#define NB 8
#define SQ 1024
#define SK 1024
#define DD 1024
#define NH 8
#define DH 128
#define HB (NH*NB)              // 64
#define XSIZE (NB*SQ*DD)        // 8388608
#define NEGV (-4294967295.0f)
#define SCALE 0.0883883476483184405f

// mma GEMM smem: per buffer 4 operands (Ah,Al,Bh,Bl), each 128 rows x 32 bf16,
// row stride 80B (64B data + 16B skew for conflict-free ldmatrix)
#define ROWB 80
#define OP_BYTES (128*ROWB)       // 10240
#define OFF_AL (1*OP_BYTES)
#define OFF_BH (2*OP_BYTES)
#define OFF_BL (3*OP_BYTES)
#define BUF_BYTES (4*OP_BYTES)    // 40960
#define SMEM_TOT (2*BUF_BYTES)    // 81920

// ---------------------------------------------------------------------------
// Scratch (device globals — referenced ONLY from device code)
// ---------------------------------------------------------------------------
__device__ __nv_bfloat16 g_memh[NB*SK*DD], g_meml[NB*SK*DD];
__device__ __nv_bfloat16 g_dech[NB*SQ*DD], g_decl[NB*SQ*DD];
__device__ __nv_bfloat16 g_Wkt_h[DD*DD], g_Wkt_l[DD*DD];
__device__ __nv_bfloat16 g_Wvt_h[DD*DD], g_Wvt_l[DD*DD];
__device__ __nv_bfloat16 g_Wqt_h[DD*DD], g_Wqt_l[DD*DD];
__device__ __nv_bfloat16 g_Wft_h[DD*2*DD], g_Wft_l[DD*2*DD];
__device__ __nv_bfloat16 g_Kh[HB*SK*DH], g_Kl[HB*SK*DH];
__device__ __nv_bfloat16 g_Qh[HB*SQ*DH], g_Ql[HB*SQ*DH];
__device__ float         g_V[HB*SK*DH];
__device__ __nv_bfloat16 g_Vth[HB*DH*SK], g_Vtl[HB*DH*SK];
__device__ __nv_bfloat16 g_Ph[(size_t)HB*SQ*SK], g_Pl[(size_t)HB*SQ*SK];
__device__ __nv_bfloat16 g_Oh[NB*SQ*DD], g_Ol[NB*SQ*DD];
__device__ float         g_X[NB*SQ*DD];
__device__ int           g_maskmode;

// ---------------------------------------------------------------------------
// Helpers
// ---------------------------------------------------------------------------
__device__ __forceinline__ uint32_t smem_to_u32(const void* p) {
    uint32_t a;
    asm("{ .reg .u64 t; cvta.to.shared.u64 t, %1; cvt.u32.u64 %0, t; }" : "=r"(a) : "l"(p));
    return a;
}

__device__ __forceinline__ void cp16(uint32_t dst, const void* src) {
    asm volatile("cp.async.cg.shared.global [%0], [%1], 16;" :: "r"(dst), "l"(src));
}
#define CP_COMMIT() asm volatile("cp.async.commit_group;" ::: "memory")
#define CP_WAIT(n)  asm volatile("cp.async.wait_group %0;" :: "n"(n) : "memory")

__device__ __forceinline__ void ldm_x4(uint32_t* r, uint32_t addr) {
    asm volatile("ldmatrix.sync.aligned.m8n8.x4.shared.b16 {%0,%1,%2,%3}, [%4];"
        : "=r"(r[0]), "=r"(r[1]), "=r"(r[2]), "=r"(r[3]) : "r"(addr));
}

__device__ __forceinline__ void mma16816(float* d, const uint32_t* a, const uint32_t* b) {
    asm volatile("mma.sync.aligned.m16n8k16.row.col.f32.bf16.bf16.f32 "
        "{%0,%1,%2,%3}, {%4,%5,%6,%7}, {%8,%9}, {%0,%1,%2,%3};"
        : "+f"(d[0]), "+f"(d[1]), "+f"(d[2]), "+f"(d[3])
        : "r"(a[0]), "r"(a[1]), "r"(a[2]), "r"(a[3]), "r"(b[0]), "r"(b[1]));
}

__device__ __forceinline__ void split_hilo(float v, __nv_bfloat16& h, __nv_bfloat16& l) {
    h = __float2bfloat16(v);
    l = __float2bfloat16(v - __bfloat162float(h));
}
__device__ __forceinline__ uint32_t pack2h(float v0, float v1) {
    __nv_bfloat16 h0, l0, h1, l1;
    split_hilo(v0, h0, l0); split_hilo(v1, h1, l1);
    __nv_bfloat162 p = __halves2bfloat162(h0, h1);
    return *reinterpret_cast<uint32_t*>(&p);
}
__device__ __forceinline__ uint32_t pack2l(float v0, float v1) {
    __nv_bfloat16 h0, l0, h1, l1;
    split_hilo(v0, h0, l0); split_hilo(v1, h1, l1);
    __nv_bfloat162 p = __halves2bfloat162(l0, l1);
    return *reinterpret_cast<uint32_t*>(&p);
}

// ---------------------------------------------------------------------------
// mma GEMM building blocks (bf16 hi/lo 3-term split, 128x128 tile, k-chunk 32)
// ---------------------------------------------------------------------------
__device__ __forceinline__ void load_chunk(
    uint32_t sbuf,
    const __nv_bfloat16* __restrict__ Ah, const __nv_bfloat16* __restrict__ Al,
    const __nv_bfloat16* __restrict__ Bh, const __nv_bfloat16* __restrict__ Bl,
    int lda, int ldb, int tid)
{
#pragma unroll
    for (int i = tid; i < 512; i += 256) {
        int row = i >> 2, ch = i & 3;
        uint32_t d = sbuf + row*ROWB + ch*16;
        size_t ao = (size_t)row * lda * 2 + ch*16;
        size_t bo = (size_t)row * ldb * 2 + ch*16;
        cp16(d,           (const char*)Ah + ao);
        cp16(d + OFF_AL,  (const char*)Al + ao);
        cp16(d + OFF_BH,  (const char*)Bh + bo);
        cp16(d + OFF_BL,  (const char*)Bl + bo);
    }
}

__device__ __forceinline__ void compute_chunk(uint32_t sbuf, int lane, int m0, int n0,
                                              float acc[2][8][4])
{
#pragma unroll
    for (int kk = 0; kk < 2; kk++) {
        uint32_t ah[2][4], al[2][4];
        int arow = m0 + (lane & 15);
        uint32_t abase = sbuf + kk*32 + ((lane >> 4) & 1)*16;
        ldm_x4(ah[0], abase + arow*ROWB);
        ldm_x4(ah[1], abase + (arow + 16)*ROWB);
        ldm_x4(al[0], abase + OFF_AL + arow*ROWB);
        ldm_x4(al[1], abase + OFF_AL + (arow + 16)*ROWB);

        uint32_t bh[4][4], bl[4][4];
        int brow = n0 + ((lane >> 4) << 3) + (lane & 7);
        uint32_t bko = ((lane >> 3) & 1) * 16 + kk*32;
#pragma unroll
        for (int nb = 0; nb < 4; nb++) {
            ldm_x4(bh[nb], sbuf + OFF_BH + (brow + nb*16)*ROWB + bko);
            ldm_x4(bl[nb], sbuf + OFF_BL + (brow + nb*16)*ROWB + bko);
        }
#pragma unroll
        for (int mi = 0; mi < 2; mi++)
#pragma unroll
            for (int ni = 0; ni < 8; ni++) {
                const uint32_t* BH = &bh[ni >> 1][(ni & 1) * 2];
                const uint32_t* BL = &bl[ni >> 1][(ni & 1) * 2];
                mma16816(acc[mi][ni], ah[mi], BH);
                mma16816(acc[mi][ni], al[mi], BH);
                mma16816(acc[mi][ni], ah[mi], BL);
            }
    }
}

#define ACC_ZERO() do { \
    _Pragma("unroll") for (int _i = 0; _i < 2; _i++) \
    _Pragma("unroll") for (int _j = 0; _j < 8; _j++) \
    _Pragma("unroll") for (int _k = 0; _k < 4; _k++) acc[_i][_j][_k] = 0.f; \
} while (0)

// ---------------------------------------------------------------------------
// Mask dtype detection
// ---------------------------------------------------------------------------
__global__ void detect_mask_kernel(const void* __restrict__ mask) {
    int t = threadIdx.x;
    const int* pi = (const int*)mask;
    const float* pf = (const float*)mask;
    bool oki = true, okf = true;
    for (int i = t; i < 256; i += 32) {
        int v = pi[i];
        oki = oki && (v == 0 || v == 1);
        float f = pf[i];
        okf = okf && (f == 0.0f || f == 1.0f);
    }
    oki = __all_sync(0xFFFFFFFFu, oki);
    okf = __all_sync(0xFFFFFFFFu, okf);
    if (t == 0) g_maskmode = oki ? 0 : (okf ? 1 : 2);
}

// ---------------------------------------------------------------------------
// fp32 -> bf16 hi/lo. which=0 -> g_mem*, which=1 -> g_dec*  (device-resolved!)
// ---------------------------------------------------------------------------
__global__ void conv_hilo_kernel(const float* __restrict__ src, int which, int n4) {
    __nv_bfloat16* __restrict__ dh = which ? g_dech : g_memh;
    __nv_bfloat16* __restrict__ dl = which ? g_decl : g_meml;
    int idx = blockIdx.x * blockDim.x + threadIdx.x;
    if (idx >= n4) return;
    float4 v = ((const float4*)src)[idx];
    uint2 hw, lw;
    hw.x = pack2h(v.x, v.y); hw.y = pack2h(v.z, v.w);
    lw.x = pack2l(v.x, v.y); lw.y = pack2l(v.z, v.w);
    ((uint2*)dh)[idx] = hw;
    ((uint2*)dl)[idx] = lw;
}

// ---------------------------------------------------------------------------
// W [K][N] fp32 -> Wt [N][K] bf16 hi/lo. which: 0=Wk 1=Wv 2=Wq 3=Wf (device-resolved)
// ---------------------------------------------------------------------------
__global__ void convT_kernel(const float* __restrict__ src, int which, int K, int N) {
    __nv_bfloat16 *dh, *dl;
    if (which == 0)      { dh = g_Wkt_h; dl = g_Wkt_l; }
    else if (which == 1) { dh = g_Wvt_h; dl = g_Wvt_l; }
    else if (which == 2) { dh = g_Wqt_h; dl = g_Wqt_l; }
    else                 { dh = g_Wft_h; dl = g_Wft_l; }

    __shared__ float t[32][33];
    int n0 = blockIdx.x * 32, k0 = blockIdx.y * 32;
    int tx = threadIdx.x;
    for (int i = threadIdx.y; i < 32; i += 8)
        t[i][tx] = src[(size_t)(k0 + i) * N + n0 + tx];
    __syncthreads();
    for (int i = threadIdx.y; i < 32; i += 8) {
        float v = t[tx][i];
        __nv_bfloat16 h, l;
        split_hilo(v, h, l);
        size_t o = (size_t)(n0 + i) * K + k0 + tx;
        dh[o] = h; dl[o] = l;
    }
}

// ---------------------------------------------------------------------------
// V [hb][1024][128] fp32 -> Vt [hb][128][1024] bf16 hi/lo
// ---------------------------------------------------------------------------
__global__ void transposeV_kernel() {
    __shared__ float t[32][33];
    int hb = blockIdx.z;
    int d0 = blockIdx.x * 32, s0 = blockIdx.y * 32;
    int tx = threadIdx.x;
    const float* src = g_V + (size_t)hb * SK * DH;
    for (int i = threadIdx.y; i < 32; i += 8)
        t[i][tx] = src[(size_t)(s0 + i) * 128 + d0 + tx];
    __syncthreads();
    for (int i = threadIdx.y; i < 32; i += 8) {
        float v = t[tx][i];
        __nv_bfloat16 h, l;
        split_hilo(v, h, l);
        size_t o = (size_t)hb * DH * SK + (size_t)(d0 + i) * 1024 + s0 + tx;
        g_Vth[o] = h; g_Vtl[o] = l;
    }
}

// ---------------------------------------------------------------------------
// Projection GEMM (HMMA): z=0 K, z=1 V (fp32 out), z=2 Q. Head-split outputs.
// ---------------------------------------------------------------------------
__global__ __launch_bounds__(256, 1) void proj_mma_kernel() {
    extern __shared__ char smem[];
    uint32_t sb = smem_to_u32(smem);
    int tid = threadIdx.x, lane = tid & 31, w = tid >> 5;
    int m0 = (w & 3) * 32, n0 = (w >> 2) * 64;
    int bx = blockIdx.x, by = blockIdx.y, z = blockIdx.z;

    const __nv_bfloat16* Ah = ((z == 2) ? g_dech : g_memh) + (size_t)by * 128 * 1024;
    const __nv_bfloat16* Al = ((z == 2) ? g_decl : g_meml) + (size_t)by * 128 * 1024;
    const __nv_bfloat16* Bh = ((z == 0) ? g_Wkt_h : ((z == 1) ? g_Wvt_h : g_Wqt_h)) + (size_t)bx * 128 * 1024;
    const __nv_bfloat16* Bl = ((z == 0) ? g_Wkt_l : ((z == 1) ? g_Wvt_l : g_Wqt_l)) + (size_t)bx * 128 * 1024;

    float acc[2][8][4];
    ACC_ZERO();

    const int KC = 32;
    load_chunk(sb, Ah, Al, Bh, Bl, 1024, 1024, tid);
    CP_COMMIT();
    for (int c = 0; c < KC; c++) {
        if (c + 1 < KC) {
            int k0 = (c + 1) * 32;
            load_chunk(sb + ((c + 1) & 1) * BUF_BYTES, Ah + k0, Al + k0, Bh + k0, Bl + k0,
                       1024, 1024, tid);
            CP_COMMIT();
            CP_WAIT(1);
        } else CP_WAIT(0);
        __syncthreads();
        compute_chunk(sb + (c & 1) * BUF_BYTES, lane, m0, n0, acc);
        __syncthreads();
    }

#pragma unroll
    for (int mi = 0; mi < 2; mi++)
#pragma unroll
        for (int ni = 0; ni < 8; ni++) {
            int cc = n0 + ni * 8 + (lane & 3) * 2;       // d within head (head = bx)
#pragma unroll
            for (int half = 0; half < 2; half++) {
                int rr = by * 128 + m0 + mi * 16 + (lane >> 2) + half * 8;
                float d0 = acc[mi][ni][half * 2], d1 = acc[mi][ni][half * 2 + 1];
                int bb = rr >> 10, ss = rr & 1023;
                size_t base = (((size_t)(bx * 8 + bb)) * 1024 + ss) * 128 + cc;
                if (z == 1) {
                    *(float2*)(g_V + base) = make_float2(d0, d1);
                } else {
                    __nv_bfloat16* oh = (z == 0) ? g_Kh : g_Qh;
                    __nv_bfloat16* ol = (z == 0) ? g_Kl : g_Ql;
                    *(uint32_t*)(oh + base) = pack2h(d0, d1);
                    *(uint32_t*)(ol + base) = pack2l(d0, d1);
                }
            }
        }
}

// ---------------------------------------------------------------------------
// Scores GEMM (HMMA): S = Q @ K^T * scale  -> attn region (fp32)
// ---------------------------------------------------------------------------
__global__ __launch_bounds__(256, 1) void scores_mma_kernel(float* __restrict__ attn) {
    extern __shared__ char smem[];
    uint32_t sb = smem_to_u32(smem);
    int tid = threadIdx.x, lane = tid & 31, w = tid >> 5;
    int m0 = (w & 3) * 32, n0 = (w >> 2) * 64;
    int bx = blockIdx.x, by = blockIdx.y, hb = blockIdx.z;

    const __nv_bfloat16* Ah = g_Qh + ((size_t)hb * 1024 + by * 128) * 128;
    const __nv_bfloat16* Al = g_Ql + ((size_t)hb * 1024 + by * 128) * 128;
    const __nv_bfloat16* Bh = g_Kh + ((size_t)hb * 1024 + bx * 128) * 128;
    const __nv_bfloat16* Bl = g_Kl + ((size_t)hb * 1024 + bx * 128) * 128;

    float acc[2][8][4];
    ACC_ZERO();

    const int KC = 4;
    load_chunk(sb, Ah, Al, Bh, Bl, 128, 128, tid);
    CP_COMMIT();
    for (int c = 0; c < KC; c++) {
        if (c + 1 < KC) {
            int k0 = (c + 1) * 32;
            load_chunk(sb + ((c + 1) & 1) * BUF_BYTES, Ah + k0, Al + k0, Bh + k0, Bl + k0,
                       128, 128, tid);
            CP_COMMIT();
            CP_WAIT(1);
        } else CP_WAIT(0);
        __syncthreads();
        compute_chunk(sb + (c & 1) * BUF_BYTES, lane, m0, n0, acc);
        __syncthreads();
    }

#pragma unroll
    for (int mi = 0; mi < 2; mi++)
#pragma unroll
        for (int ni = 0; ni < 8; ni++) {
            int cc = bx * 128 + n0 + ni * 8 + (lane & 3) * 2;
#pragma unroll
            for (int half = 0; half < 2; half++) {
                int rr = by * 128 + m0 + mi * 16 + (lane >> 2) + half * 8;
                float d0 = acc[mi][ni][half * 2], d1 = acc[mi][ni][half * 2 + 1];
                float* op = attn + ((size_t)hb * 1024 + rr) * 1024 + cc;
                *(float2*)op = make_float2(d0 * SCALE, d1 * SCALE);
            }
        }
}

// ---------------------------------------------------------------------------
// Softmax (+ query-mask) in place; also emits P as bf16 hi/lo (device globals)
// ---------------------------------------------------------------------------
__global__ __launch_bounds__(256) void softmax_kernel(
    float* __restrict__ attn, const float* __restrict__ qmask,
    const void* __restrict__ mask) {
    const int rowid = blockIdx.x;
    const int hb = rowid >> 10;
    const int q = rowid & 1023;
    const int b = hb & 7;
    const int tid = threadIdx.x;

    float* rp = attn + (size_t)rowid * SK;
    const int mode = g_maskmode;
    const size_t moff = ((size_t)b * SQ + q) * SK + (size_t)tid * 4;

    float4 x = *(const float4*)(rp + tid * 4);
    int m0, m1, m2, m3;
    if (mode == 0) {
        int4 mv = *(const int4*)((const int*)mask + moff);
        m0 = mv.x; m1 = mv.y; m2 = mv.z; m3 = mv.w;
    } else if (mode == 1) {
        float4 mv = *(const float4*)((const float*)mask + moff);
        m0 = (mv.x != 0.f); m1 = (mv.y != 0.f); m2 = (mv.z != 0.f); m3 = (mv.w != 0.f);
    } else {
        uchar4 mv = *(const uchar4*)((const unsigned char*)mask + moff);
        m0 = mv.x; m1 = mv.y; m2 = mv.z; m3 = mv.w;
    }
    float v0 = m0 ? NEGV : x.x;
    float v1 = m1 ? NEGV : x.y;
    float v2 = m2 ? NEGV : x.z;
    float v3 = m3 ? NEGV : x.w;

    __shared__ float red[256];
    float mx = fmaxf(fmaxf(v0, v1), fmaxf(v2, v3));
    red[tid] = mx;
    __syncthreads();
#pragma unroll
    for (int s = 128; s > 0; s >>= 1) {
        if (tid < s) red[tid] = fmaxf(red[tid], red[tid + s]);
        __syncthreads();
    }
    float rowmax = red[0];
    __syncthreads();

    float e0 = expf(v0 - rowmax);
    float e1 = expf(v1 - rowmax);
    float e2 = expf(v2 - rowmax);
    float e3 = expf(v3 - rowmax);
    red[tid] = e0 + e1 + e2 + e3;
    __syncthreads();
#pragma unroll
    for (int s = 128; s > 0; s >>= 1) {
        if (tid < s) red[tid] += red[tid + s];
        __syncthreads();
    }
    float total = red[0];

    float qm = qmask[b * SQ + q];
    float inv = qm / total;
    float p0 = e0 * inv, p1 = e1 * inv, p2 = e2 * inv, p3 = e3 * inv;
    *(float4*)(rp + tid * 4) = make_float4(p0, p1, p2, p3);

    size_t po = (size_t)rowid * 1024 + tid * 4;
    uint2 hw, lw;
    hw.x = pack2h(p0, p1); hw.y = pack2h(p2, p3);
    lw.x = pack2l(p0, p1); lw.y = pack2l(p2, p3);
    *(uint2*)(g_Ph + po) = hw;
    *(uint2*)(g_Pl + po) = lw;
}

// ---------------------------------------------------------------------------
// PV GEMM (HMMA): O = P @ V   (B = Vt[hb][128][1024]); bf16 hi/lo out
// ---------------------------------------------------------------------------
__global__ __launch_bounds__(256, 1) void pv_mma_kernel() {
    extern __shared__ char smem[];
    uint32_t sb = smem_to_u32(smem);
    int tid = threadIdx.x, lane = tid & 31, w = tid >> 5;
    int m0 = (w & 3) * 32, n0 = (w >> 2) * 64;
    int bx = blockIdx.x, hb = blockIdx.y;

    const __nv_bfloat16* Ah = g_Ph + ((size_t)hb * 1024 + bx * 128) * 1024;
    const __nv_bfloat16* Al = g_Pl + ((size_t)hb * 1024 + bx * 128) * 1024;
    const __nv_bfloat16* Bh = g_Vth + (size_t)hb * DH * SK;
    const __nv_bfloat16* Bl = g_Vtl + (size_t)hb * DH * SK;

    float acc[2][8][4];
    ACC_ZERO();

    const int KC = 32;
    load_chunk(sb, Ah, Al, Bh, Bl, 1024, 1024, tid);
    CP_COMMIT();
    for (int c = 0; c < KC; c++) {
        if (c + 1 < KC) {
            int k0 = (c + 1) * 32;
            load_chunk(sb + ((c + 1) & 1) * BUF_BYTES, Ah + k0, Al + k0, Bh + k0, Bl + k0,
                       1024, 1024, tid);
            CP_COMMIT();
            CP_WAIT(1);
        } else CP_WAIT(0);
        __syncthreads();
        compute_chunk(sb + (c & 1) * BUF_BYTES, lane, m0, n0, acc);
        __syncthreads();
    }

    const int b = hb & 7, h = hb >> 3;
#pragma unroll
    for (int mi = 0; mi < 2; mi++)
#pragma unroll
        for (int ni = 0; ni < 8; ni++) {
            int cc = n0 + ni * 8 + (lane & 3) * 2;       // d 0..127
#pragma unroll
            for (int half = 0; half < 2; half++) {
                int q = bx * 128 + m0 + mi * 16 + (lane >> 2) + half * 8;
                float d0 = acc[mi][ni][half * 2], d1 = acc[mi][ni][half * 2 + 1];
                size_t base = ((size_t)b * 1024 + q) * 1024 + h * 128 + cc;
                *(uint32_t*)(g_Oh + base) = pack2h(d0, d1);
                *(uint32_t*)(g_Ol + base) = pack2l(d0, d1);
            }
        }
}

// ---------------------------------------------------------------------------
// Final GEMM (HMMA): X = [dec | O] @ Wf + bf + dec  (K = 2048)
// ---------------------------------------------------------------------------
__global__ __launch_bounds__(256, 1) void final_mma_kernel(
    const float* __restrict__ dec, const float* __restrict__ bf) {
    extern __shared__ char smem[];
    uint32_t sb = smem_to_u32(smem);
    int tid = threadIdx.x, lane = tid & 31, w = tid >> 5;
    int m0 = (w & 3) * 32, n0 = (w >> 2) * 64;
    int bx = blockIdx.x, by = blockIdx.y;
    const size_t arow0 = (size_t)by * 128;

    const __nv_bfloat16* Bh = g_Wft_h + (size_t)bx * 128 * 2048;
    const __nv_bfloat16* Bl = g_Wft_l + (size_t)bx * 128 * 2048;

    float acc[2][8][4];
    ACC_ZERO();

    const int KC = 64;
    load_chunk(sb, g_dech + arow0 * 1024, g_decl + arow0 * 1024, Bh, Bl, 1024, 2048, tid);
    CP_COMMIT();
    for (int c = 0; c < KC; c++) {
        if (c + 1 < KC) {
            int k0 = (c + 1) * 32;
            const __nv_bfloat16 *pAh, *pAl;
            if (k0 < 1024) {
                pAh = g_dech + arow0 * 1024 + k0;
                pAl = g_decl + arow0 * 1024 + k0;
            } else {
                pAh = g_Oh + arow0 * 1024 + (k0 - 1024);
                pAl = g_Ol + arow0 * 1024 + (k0 - 1024);
            }
            load_chunk(sb + ((c + 1) & 1) * BUF_BYTES, pAh, pAl, Bh + k0, Bl + k0,
                       1024, 2048, tid);
            CP_COMMIT();
            CP_WAIT(1);
        } else CP_WAIT(0);
        __syncthreads();
        compute_chunk(sb + (c & 1) * BUF_BYTES, lane, m0, n0, acc);
        __syncthreads();
    }

#pragma unroll
    for (int mi = 0; mi < 2; mi++)
#pragma unroll
        for (int ni = 0; ni < 8; ni++) {
            int cc = bx * 128 + n0 + ni * 8 + (lane & 3) * 2;
            float2 bv = *(const float2*)(bf + cc);
#pragma unroll
            for (int half = 0; half < 2; half++) {
                int rr = by * 128 + m0 + mi * 16 + (lane >> 2) + half * 8;
                float d0 = acc[mi][ni][half * 2], d1 = acc[mi][ni][half * 2 + 1];
                float2 dv = *(const float2*)(dec + (size_t)rr * 1024 + cc);
                *(float2*)(g_X + (size_t)rr * 1024 + cc) =
                    make_float2(d0 + bv.x + dv.x, d1 + bv.y + dv.y);
            }
        }
}

// ---------------------------------------------------------------------------
// LayerNorm
// ---------------------------------------------------------------------------
__global__ __launch_bounds__(256) void ln_kernel(
    const float* __restrict__ gamma, const float* __restrict__ beta,
    float* __restrict__ out) {
    const int rowid = blockIdx.x;
    const int tid = threadIdx.x;
    const float* rp = g_X + (size_t)rowid * 1024;

    float4 x = *(const float4*)(rp + tid * 4);
    __shared__ float red[256];
    red[tid] = x.x + x.y + x.z + x.w;
    __syncthreads();
#pragma unroll
    for (int s = 128; s > 0; s >>= 1) {
        if (tid < s) red[tid] += red[tid + s];
        __syncthreads();
    }
    float mean = red[0] * (1.0f / 1024.0f);
    __syncthreads();

    float d0 = x.x - mean, d1 = x.y - mean, d2 = x.z - mean, d3 = x.w - mean;
    red[tid] = d0 * d0 + d1 * d1 + d2 * d2 + d3 * d3;
    __syncthreads();
#pragma unroll
    for (int s = 128; s > 0; s >>= 1) {
        if (tid < s) red[tid] += red[tid + s];
        __syncthreads();
    }
    float var = red[0] * (1.0f / 1024.0f);
    float inv = rsqrtf(var + 1e-5f);

    float4 g = *(const float4*)(gamma + tid * 4);
    float4 bt = *(const float4*)(beta + tid * 4);
    float* optr = out + (size_t)rowid * 1024 + tid * 4;
    *(float4*)optr = make_float4(d0 * inv * g.x + bt.x,
                                 d1 * inv * g.y + bt.y,
                                 d2 * inv * g.z + bt.z,
                                 d3 * inv * g.w + bt.w);
}

// ---------------------------------------------------------------------------
extern "C" void kernel_launch(void* const* d_in, const int* in_sizes, int n_in,
                              void* d_out, int out_size) {
    (void)in_sizes; (void)n_in; (void)out_size;
    const float* mem   = (const float*)d_in[0];
    const float* dec   = (const float*)d_in[1];
    const float* qmask = (const float*)d_in[2];
    const float* Wk    = (const float*)d_in[3];
    const float* Wv    = (const float*)d_in[4];
    const float* Wq    = (const float*)d_in[5];
    const float* Wf    = (const float*)d_in[6];
    const float* bf    = (const float*)d_in[7];
    const float* gamma = (const float*)d_in[8];
    const float* beta  = (const float*)d_in[9];
    const void*  mask  = d_in[10];

    float* out  = (float*)d_out;
    float* attn = out + XSIZE;

    cudaFuncSetAttribute(proj_mma_kernel,   cudaFuncAttributeMaxDynamicSharedMemorySize, SMEM_TOT);
    cudaFuncSetAttribute(scores_mma_kernel, cudaFuncAttributeMaxDynamicSharedMemorySize, SMEM_TOT);
    cudaFuncSetAttribute(pv_mma_kernel,     cudaFuncAttributeMaxDynamicSharedMemorySize, SMEM_TOT);
    cudaFuncSetAttribute(final_mma_kernel,  cudaFuncAttributeMaxDynamicSharedMemorySize, SMEM_TOT);

    detect_mask_kernel<<<1, 32>>>(mask);
    conv_hilo_kernel<<<8192, 256>>>(mem, 0, XSIZE / 4);
    conv_hilo_kernel<<<8192, 256>>>(dec, 1, XSIZE / 4);
    convT_kernel<<<dim3(32, 32), dim3(32, 8)>>>(Wk, 0, 1024, 1024);
    convT_kernel<<<dim3(32, 32), dim3(32, 8)>>>(Wv, 1, 1024, 1024);
    convT_kernel<<<dim3(32, 32), dim3(32, 8)>>>(Wq, 2, 1024, 1024);
    convT_kernel<<<dim3(32, 64), dim3(32, 8)>>>(Wf, 3, 2048, 1024);

    proj_mma_kernel<<<dim3(8, 64, 3), 256, SMEM_TOT>>>();
    transposeV_kernel<<<dim3(4, 32, 64), dim3(32, 8)>>>();
    scores_mma_kernel<<<dim3(8, 8, 64), 256, SMEM_TOT>>>(attn);
    softmax_kernel<<<65536, 256>>>(attn, qmask, mask);
    pv_mma_kernel<<<dim3(8, 64), 256, SMEM_TOT>>>();
    final_mma_kernel<<<dim3(8, 64), 256, SMEM_TOT>>>(dec, bf);
    ln_kernel<<<8192, 256>>>(gamma, beta, out);
}

// round 7
// speedup vs baseline: 2.6103x; 1.2467x over previous
#include <cuda_runtime.h>
#include <cuda_bf16.h>
#include <cstdint>
#include <math.h>

// ---------------------------------------------------------------------------
// Problem constants
// ---------------------------------------------------------------------------
#define NB 8
#define SQ 1024
#define SK 1024
#define DD 1024
#define NH 8
#define DH 128
#define HB (NH*NB)              // 64
#define XSIZE (NB*SQ*DD)        // 8388608
#define NEGV (-4294967295.0f)
#define SCALE 0.0883883476483184405f

// mma GEMM smem: per buffer 4 operand slots (Ah,Al,Bh,Bl), each 128 rows x 32 bf16,
// row stride 80B (64B data + 16B skew for conflict-free ldmatrix). 3-stage pipeline.
#define ROWB 80
#define OP_BYTES (128*ROWB)       // 10240
#define OFF_AL (1*OP_BYTES)
#define OFF_BH (2*OP_BYTES)
#define OFF_BL (3*OP_BYTES)
#define BUF_BYTES (4*OP_BYTES)    // 40960
#define SMEM_TOT (3*BUF_BYTES)    // 122880

// ---------------------------------------------------------------------------
// Scratch (device globals — referenced ONLY from device code)
// ---------------------------------------------------------------------------
__device__ __nv_bfloat16 g_memh[NB*SK*DD], g_meml[NB*SK*DD];
__device__ __nv_bfloat16 g_dech[NB*SQ*DD], g_decl[NB*SQ*DD];
__device__ __nv_bfloat16 g_Wkt_h[DD*DD], g_Wkt_l[DD*DD];
__device__ __nv_bfloat16 g_Wvt_h[DD*DD];
__device__ __nv_bfloat16 g_Wqt_h[DD*DD], g_Wqt_l[DD*DD];
__device__ __nv_bfloat16 g_Wft_h[DD*2*DD], g_Wft_l[DD*2*DD];
__device__ __nv_bfloat16 g_Kh[HB*SK*DH], g_Kl[HB*SK*DH];
__device__ __nv_bfloat16 g_Qh[HB*SQ*DH], g_Ql[HB*SQ*DH];
__device__ float         g_V[HB*SK*DH];
__device__ __nv_bfloat16 g_Vth[HB*DH*SK];
__device__ __nv_bfloat16 g_Ph[(size_t)HB*SQ*SK];
__device__ __nv_bfloat16 g_Oh[NB*SQ*DD];
__device__ float         g_X[NB*SQ*DD];
__device__ int           g_maskmode;

// ---------------------------------------------------------------------------
// Helpers
// ---------------------------------------------------------------------------
__device__ __forceinline__ uint32_t smem_to_u32(const void* p) {
    uint32_t a;
    asm("{ .reg .u64 t; cvta.to.shared.u64 t, %1; cvt.u32.u64 %0, t; }" : "=r"(a) : "l"(p));
    return a;
}

__device__ __forceinline__ void cp16(uint32_t dst, const void* src) {
    asm volatile("cp.async.cg.shared.global [%0], [%1], 16;" :: "r"(dst), "l"(src));
}
#define CP_COMMIT() asm volatile("cp.async.commit_group;" ::: "memory")
#define CP_WAIT(n)  asm volatile("cp.async.wait_group %0;" :: "n"(n) : "memory")

__device__ __forceinline__ void ldm_x4(uint32_t* r, uint32_t addr) {
    asm volatile("ldmatrix.sync.aligned.m8n8.x4.shared.b16 {%0,%1,%2,%3}, [%4];"
        : "=r"(r[0]), "=r"(r[1]), "=r"(r[2]), "=r"(r[3]) : "r"(addr));
}

__device__ __forceinline__ void mma16816(float* d, const uint32_t* a, const uint32_t* b) {
    asm volatile("mma.sync.aligned.m16n8k16.row.col.f32.bf16.bf16.f32 "
        "{%0,%1,%2,%3}, {%4,%5,%6,%7}, {%8,%9}, {%0,%1,%2,%3};"
        : "+f"(d[0]), "+f"(d[1]), "+f"(d[2]), "+f"(d[3])
        : "r"(a[0]), "r"(a[1]), "r"(a[2]), "r"(a[3]), "r"(b[0]), "r"(b[1]));
}

__device__ __forceinline__ void split_hilo(float v, __nv_bfloat16& h, __nv_bfloat16& l) {
    h = __float2bfloat16(v);
    l = __float2bfloat16(v - __bfloat162float(h));
}
__device__ __forceinline__ uint32_t pack2h(float v0, float v1) {
    __nv_bfloat16 h0, l0, h1, l1;
    split_hilo(v0, h0, l0); split_hilo(v1, h1, l1);
    __nv_bfloat162 p = __halves2bfloat162(h0, h1);
    return *reinterpret_cast<uint32_t*>(&p);
}
__device__ __forceinline__ uint32_t pack2l(float v0, float v1) {
    __nv_bfloat16 h0, l0, h1, l1;
    split_hilo(v0, h0, l0); split_hilo(v1, h1, l1);
    __nv_bfloat162 p = __halves2bfloat162(l0, l1);
    return *reinterpret_cast<uint32_t*>(&p);
}

// ---------------------------------------------------------------------------
// mma GEMM building blocks. TERMS=3: hi/lo split (Ah·Bh + Al·Bh + Ah·Bl);
// TERMS=1: single bf16 (Ah·Bh only — Al/Bl slots untouched).
// ---------------------------------------------------------------------------
template<int TERMS>
__device__ __forceinline__ void load_chunk_t(
    uint32_t sbuf,
    const __nv_bfloat16* __restrict__ Ah, const __nv_bfloat16* __restrict__ Al,
    const __nv_bfloat16* __restrict__ Bh, const __nv_bfloat16* __restrict__ Bl,
    int lda, int ldb, int tid)
{
#pragma unroll
    for (int i = tid; i < 512; i += 256) {
        int row = i >> 2, ch = i & 3;
        uint32_t d = sbuf + row*ROWB + ch*16;
        size_t ao = (size_t)row * lda * 2 + ch*16;
        size_t bo = (size_t)row * ldb * 2 + ch*16;
        cp16(d,           (const char*)Ah + ao);
        cp16(d + OFF_BH,  (const char*)Bh + bo);
        if (TERMS == 3) {
            cp16(d + OFF_AL,  (const char*)Al + ao);
            cp16(d + OFF_BL,  (const char*)Bl + bo);
        }
    }
}

template<int TERMS>
__device__ __forceinline__ void compute_chunk_t(uint32_t sbuf, int lane, int m0, int n0,
                                                float acc[2][8][4])
{
#pragma unroll
    for (int kk = 0; kk < 2; kk++) {
        uint32_t ah[2][4], al[2][4];
        int arow = m0 + (lane & 15);
        uint32_t abase = sbuf + kk*32 + ((lane >> 4) & 1)*16;
        ldm_x4(ah[0], abase + arow*ROWB);
        ldm_x4(ah[1], abase + (arow + 16)*ROWB);
        if (TERMS == 3) {
            ldm_x4(al[0], abase + OFF_AL + arow*ROWB);
            ldm_x4(al[1], abase + OFF_AL + (arow + 16)*ROWB);
        }

        uint32_t bh[4][4], bl[4][4];
        int brow = n0 + ((lane >> 4) << 3) + (lane & 7);
        uint32_t bko = ((lane >> 3) & 1) * 16 + kk*32;
#pragma unroll
        for (int nb = 0; nb < 4; nb++) {
            ldm_x4(bh[nb], sbuf + OFF_BH + (brow + nb*16)*ROWB + bko);
            if (TERMS == 3)
                ldm_x4(bl[nb], sbuf + OFF_BL + (brow + nb*16)*ROWB + bko);
        }
#pragma unroll
        for (int mi = 0; mi < 2; mi++)
#pragma unroll
            for (int ni = 0; ni < 8; ni++) {
                const uint32_t* BH = &bh[ni >> 1][(ni & 1) * 2];
                mma16816(acc[mi][ni], ah[mi], BH);
                if (TERMS == 3) {
                    const uint32_t* BL = &bl[ni >> 1][(ni & 1) * 2];
                    mma16816(acc[mi][ni], al[mi], BH);
                    mma16816(acc[mi][ni], ah[mi], BL);
                }
            }
    }
}

#define ACC_ZERO() do { \
    _Pragma("unroll") for (int _i = 0; _i < 2; _i++) \
    _Pragma("unroll") for (int _j = 0; _j < 8; _j++) \
    _Pragma("unroll") for (int _k = 0; _k < 4; _k++) acc[_i][_j][_k] = 0.f; \
} while (0)

// ---------------------------------------------------------------------------
// Mask dtype detection
// ---------------------------------------------------------------------------
__global__ void detect_mask_kernel(const void* __restrict__ mask) {
    int t = threadIdx.x;
    const int* pi = (const int*)mask;
    const float* pf = (const float*)mask;
    bool oki = true, okf = true;
    for (int i = t; i < 256; i += 32) {
        int v = pi[i];
        oki = oki && (v == 0 || v == 1);
        float f = pf[i];
        okf = okf && (f == 0.0f || f == 1.0f);
    }
    oki = __all_sync(0xFFFFFFFFu, oki);
    okf = __all_sync(0xFFFFFFFFu, okf);
    if (t == 0) g_maskmode = oki ? 0 : (okf ? 1 : 2);
}

// ---------------------------------------------------------------------------
// fp32 -> bf16 hi/lo. which=0 -> g_mem*, which=1 -> g_dec* (device-resolved)
// ---------------------------------------------------------------------------
__global__ void conv_hilo_kernel(const float* __restrict__ src, int which, int n4) {
    __nv_bfloat16* __restrict__ dh = which ? g_dech : g_memh;
    __nv_bfloat16* __restrict__ dl = which ? g_decl : g_meml;
    int idx = blockIdx.x * blockDim.x + threadIdx.x;
    if (idx >= n4) return;
    float4 v = ((const float4*)src)[idx];
    uint2 hw, lw;
    hw.x = pack2h(v.x, v.y); hw.y = pack2h(v.z, v.w);
    lw.x = pack2l(v.x, v.y); lw.y = pack2l(v.z, v.w);
    ((uint2*)dh)[idx] = hw;
    ((uint2*)dl)[idx] = lw;
}

// ---------------------------------------------------------------------------
// W [K][N] fp32 -> Wt [N][K] bf16 hi/lo. which: 0=Wk 1=Wv(hi only) 2=Wq 3=Wf
// ---------------------------------------------------------------------------
__global__ void convT_kernel(const float* __restrict__ src, int which, int K, int N) {
    __nv_bfloat16 *dh, *dl;
    if (which == 0)      { dh = g_Wkt_h; dl = g_Wkt_l; }
    else if (which == 1) { dh = g_Wvt_h; dl = nullptr; }
    else if (which == 2) { dh = g_Wqt_h; dl = g_Wqt_l; }
    else                 { dh = g_Wft_h; dl = g_Wft_l; }

    __shared__ float t[32][33];
    int n0 = blockIdx.x * 32, k0 = blockIdx.y * 32;
    int tx = threadIdx.x;
    for (int i = threadIdx.y; i < 32; i += 8)
        t[i][tx] = src[(size_t)(k0 + i) * N + n0 + tx];
    __syncthreads();
    for (int i = threadIdx.y; i < 32; i += 8) {
        float v = t[tx][i];
        __nv_bfloat16 h, l;
        split_hilo(v, h, l);
        size_t o = (size_t)(n0 + i) * K + k0 + tx;
        dh[o] = h;
        if (dl) dl[o] = l;
    }
}

// ---------------------------------------------------------------------------
// V [hb][1024][128] fp32 -> Vt [hb][128][1024] bf16 (hi only)
// ---------------------------------------------------------------------------
__global__ void transposeV_kernel() {
    __shared__ float t[32][33];
    int hb = blockIdx.z;
    int d0 = blockIdx.x * 32, s0 = blockIdx.y * 32;
    int tx = threadIdx.x;
    const float* src = g_V + (size_t)hb * SK * DH;
    for (int i = threadIdx.y; i < 32; i += 8)
        t[i][tx] = src[(size_t)(s0 + i) * 128 + d0 + tx];
    __syncthreads();
    for (int i = threadIdx.y; i < 32; i += 8) {
        size_t o = (size_t)hb * DH * SK + (size_t)(d0 + i) * 1024 + s0 + tx;
        g_Vth[o] = __float2bfloat16(t[tx][i]);
    }
}

// 3-stage pipeline driver macro: LOADC(c, buf) must expand to the per-chunk load.
#define PIPELINE3(KC, LOADC, COMPUTEC) do { \
    { LOADC(0, sb + 0*BUF_BYTES); } CP_COMMIT(); \
    { LOADC(1, sb + 1*BUF_BYTES); } CP_COMMIT(); \
    for (int c = 0; c < (KC); c++) { \
        if (c + 2 < (KC)) { LOADC((c + 2), sb + ((c + 2) % 3)*BUF_BYTES); } \
        CP_COMMIT(); \
        CP_WAIT(2); \
        __syncthreads(); \
        { COMPUTEC(c, sb + (c % 3)*BUF_BYTES); } \
        __syncthreads(); \
    } \
} while (0)

// ---------------------------------------------------------------------------
// Projection GEMM K/Q (HMMA, 3-term): z=0 K, z=1 Q. Head-split bf16 hi/lo out.
// ---------------------------------------------------------------------------
__global__ __launch_bounds__(256, 1) void projKQ_mma_kernel() {
    extern __shared__ char smem[];
    uint32_t sb = smem_to_u32(smem);
    int tid = threadIdx.x, lane = tid & 31, w = tid >> 5;
    int m0 = (w & 3) * 32, n0 = (w >> 2) * 64;
    int bx = blockIdx.x, by = blockIdx.y, z = blockIdx.z;

    const __nv_bfloat16* Ah = ((z == 1) ? g_dech : g_memh) + (size_t)by * 128 * 1024;
    const __nv_bfloat16* Al = ((z == 1) ? g_decl : g_meml) + (size_t)by * 128 * 1024;
    const __nv_bfloat16* Bh = ((z == 0) ? g_Wkt_h : g_Wqt_h) + (size_t)bx * 128 * 1024;
    const __nv_bfloat16* Bl = ((z == 0) ? g_Wkt_l : g_Wqt_l) + (size_t)bx * 128 * 1024;

    float acc[2][8][4];
    ACC_ZERO();

#define LOADC(cc, buf) load_chunk_t<3>((buf), Ah + (cc)*32, Al + (cc)*32, Bh + (cc)*32, Bl + (cc)*32, 1024, 1024, tid)
#define COMPUTEC(cc, buf) compute_chunk_t<3>((buf), lane, m0, n0, acc)
    PIPELINE3(32, LOADC, COMPUTEC);
#undef LOADC
#undef COMPUTEC

#pragma unroll
    for (int mi = 0; mi < 2; mi++)
#pragma unroll
        for (int ni = 0; ni < 8; ni++) {
            int cc = n0 + ni * 8 + (lane & 3) * 2;       // d within head (head = bx)
#pragma unroll
            for (int half = 0; half < 2; half++) {
                int rr = by * 128 + m0 + mi * 16 + (lane >> 2) + half * 8;
                float d0 = acc[mi][ni][half * 2], d1 = acc[mi][ni][half * 2 + 1];
                int bb = rr >> 10, ss = rr & 1023;
                size_t base = (((size_t)(bx * 8 + bb)) * 1024 + ss) * 128 + cc;
                __nv_bfloat16* oh = (z == 0) ? g_Kh : g_Qh;
                __nv_bfloat16* ol = (z == 0) ? g_Kl : g_Ql;
                *(uint32_t*)(oh + base) = pack2h(d0, d1);
                *(uint32_t*)(ol + base) = pack2l(d0, d1);
            }
        }
}

// ---------------------------------------------------------------------------
// Projection GEMM V (HMMA, 1-term): fp32 head-split out
// ---------------------------------------------------------------------------
__global__ __launch_bounds__(256, 1) void projV_mma_kernel() {
    extern __shared__ char smem[];
    uint32_t sb = smem_to_u32(smem);
    int tid = threadIdx.x, lane = tid & 31, w = tid >> 5;
    int m0 = (w & 3) * 32, n0 = (w >> 2) * 64;
    int bx = blockIdx.x, by = blockIdx.y;

    const __nv_bfloat16* Ah = g_memh + (size_t)by * 128 * 1024;
    const __nv_bfloat16* Bh = g_Wvt_h + (size_t)bx * 128 * 1024;

    float acc[2][8][4];
    ACC_ZERO();

#define LOADC(cc, buf) load_chunk_t<1>((buf), Ah + (cc)*32, nullptr, Bh + (cc)*32, nullptr, 1024, 1024, tid)
#define COMPUTEC(cc, buf) compute_chunk_t<1>((buf), lane, m0, n0, acc)
    PIPELINE3(32, LOADC, COMPUTEC);
#undef LOADC
#undef COMPUTEC

#pragma unroll
    for (int mi = 0; mi < 2; mi++)
#pragma unroll
        for (int ni = 0; ni < 8; ni++) {
            int cc = n0 + ni * 8 + (lane & 3) * 2;
#pragma unroll
            for (int half = 0; half < 2; half++) {
                int rr = by * 128 + m0 + mi * 16 + (lane >> 2) + half * 8;
                float d0 = acc[mi][ni][half * 2], d1 = acc[mi][ni][half * 2 + 1];
                int bb = rr >> 10, ss = rr & 1023;
                size_t base = (((size_t)(bx * 8 + bb)) * 1024 + ss) * 128 + cc;
                *(float2*)(g_V + base) = make_float2(d0, d1);
            }
        }
}

// ---------------------------------------------------------------------------
// Scores GEMM (HMMA, 3-term): S = Q @ K^T * scale -> attn region (fp32)
// ---------------------------------------------------------------------------
__global__ __launch_bounds__(256, 1) void scores_mma_kernel(float* __restrict__ attn) {
    extern __shared__ char smem[];
    uint32_t sb = smem_to_u32(smem);
    int tid = threadIdx.x, lane = tid & 31, w = tid >> 5;
    int m0 = (w & 3) * 32, n0 = (w >> 2) * 64;
    int bx = blockIdx.x, by = blockIdx.y, hb = blockIdx.z;

    const __nv_bfloat16* Ah = g_Qh + ((size_t)hb * 1024 + by * 128) * 128;
    const __nv_bfloat16* Al = g_Ql + ((size_t)hb * 1024 + by * 128) * 128;
    const __nv_bfloat16* Bh = g_Kh + ((size_t)hb * 1024 + bx * 128) * 128;
    const __nv_bfloat16* Bl = g_Kl + ((size_t)hb * 1024 + bx * 128) * 128;

    float acc[2][8][4];
    ACC_ZERO();

#define LOADC(cc, buf) load_chunk_t<3>((buf), Ah + (cc)*32, Al + (cc)*32, Bh + (cc)*32, Bl + (cc)*32, 128, 128, tid)
#define COMPUTEC(cc, buf) compute_chunk_t<3>((buf), lane, m0, n0, acc)
    PIPELINE3(4, LOADC, COMPUTEC);
#undef LOADC
#undef COMPUTEC

#pragma unroll
    for (int mi = 0; mi < 2; mi++)
#pragma unroll
        for (int ni = 0; ni < 8; ni++) {
            int cc = bx * 128 + n0 + ni * 8 + (lane & 3) * 2;
#pragma unroll
            for (int half = 0; half < 2; half++) {
                int rr = by * 128 + m0 + mi * 16 + (lane >> 2) + half * 8;
                float d0 = acc[mi][ni][half * 2], d1 = acc[mi][ni][half * 2 + 1];
                float* op = attn + ((size_t)hb * 1024 + rr) * 1024 + cc;
                *(float2*)op = make_float2(d0 * SCALE, d1 * SCALE);
            }
        }
}

// ---------------------------------------------------------------------------
// Softmax (+ query-mask) in place; emits P as bf16 (hi only)
// ---------------------------------------------------------------------------
__global__ __launch_bounds__(256) void softmax_kernel(
    float* __restrict__ attn, const float* __restrict__ qmask,
    const void* __restrict__ mask) {
    const int rowid = blockIdx.x;
    const int hb = rowid >> 10;
    const int q = rowid & 1023;
    const int b = hb & 7;
    const int tid = threadIdx.x;

    float* rp = attn + (size_t)rowid * SK;
    const int mode = g_maskmode;
    const size_t moff = ((size_t)b * SQ + q) * SK + (size_t)tid * 4;

    float4 x = *(const float4*)(rp + tid * 4);
    int m0, m1, m2, m3;
    if (mode == 0) {
        int4 mv = *(const int4*)((const int*)mask + moff);
        m0 = mv.x; m1 = mv.y; m2 = mv.z; m3 = mv.w;
    } else if (mode == 1) {
        float4 mv = *(const float4*)((const float*)mask + moff);
        m0 = (mv.x != 0.f); m1 = (mv.y != 0.f); m2 = (mv.z != 0.f); m3 = (mv.w != 0.f);
    } else {
        uchar4 mv = *(const uchar4*)((const unsigned char*)mask + moff);
        m0 = mv.x; m1 = mv.y; m2 = mv.z; m3 = mv.w;
    }
    float v0 = m0 ? NEGV : x.x;
    float v1 = m1 ? NEGV : x.y;
    float v2 = m2 ? NEGV : x.z;
    float v3 = m3 ? NEGV : x.w;

    __shared__ float red[256];
    float mx = fmaxf(fmaxf(v0, v1), fmaxf(v2, v3));
    red[tid] = mx;
    __syncthreads();
#pragma unroll
    for (int s = 128; s > 0; s >>= 1) {
        if (tid < s) red[tid] = fmaxf(red[tid], red[tid + s]);
        __syncthreads();
    }
    float rowmax = red[0];
    __syncthreads();

    float e0 = expf(v0 - rowmax);
    float e1 = expf(v1 - rowmax);
    float e2 = expf(v2 - rowmax);
    float e3 = expf(v3 - rowmax);
    red[tid] = e0 + e1 + e2 + e3;
    __syncthreads();
#pragma unroll
    for (int s = 128; s > 0; s >>= 1) {
        if (tid < s) red[tid] += red[tid + s];
        __syncthreads();
    }
    float total = red[0];

    float qm = qmask[b * SQ + q];
    float inv = qm / total;
    float p0 = e0 * inv, p1 = e1 * inv, p2 = e2 * inv, p3 = e3 * inv;
    *(float4*)(rp + tid * 4) = make_float4(p0, p1, p2, p3);

    size_t po = (size_t)rowid * 1024 + tid * 4;
    uint2 hw;
    hw.x = pack2h(p0, p1); hw.y = pack2h(p2, p3);
    *(uint2*)(g_Ph + po) = hw;
}

// ---------------------------------------------------------------------------
// PV GEMM (HMMA, 1-term): O = P @ V  (B = Vt[hb][128][1024]); bf16 out
// ---------------------------------------------------------------------------
__global__ __launch_bounds__(256, 1) void pv_mma_kernel() {
    extern __shared__ char smem[];
    uint32_t sb = smem_to_u32(smem);
    int tid = threadIdx.x, lane = tid & 31, w = tid >> 5;
    int m0 = (w & 3) * 32, n0 = (w >> 2) * 64;
    int bx = blockIdx.x, hb = blockIdx.y;

    const __nv_bfloat16* Ah = g_Ph + ((size_t)hb * 1024 + bx * 128) * 1024;
    const __nv_bfloat16* Bh = g_Vth + (size_t)hb * DH * SK;

    float acc[2][8][4];
    ACC_ZERO();

#define LOADC(cc, buf) load_chunk_t<1>((buf), Ah + (cc)*32, nullptr, Bh + (cc)*32, nullptr, 1024, 1024, tid)
#define COMPUTEC(cc, buf) compute_chunk_t<1>((buf), lane, m0, n0, acc)
    PIPELINE3(32, LOADC, COMPUTEC);
#undef LOADC
#undef COMPUTEC

    const int b = hb & 7, h = hb >> 3;
#pragma unroll
    for (int mi = 0; mi < 2; mi++)
#pragma unroll
        for (int ni = 0; ni < 8; ni++) {
            int cc = n0 + ni * 8 + (lane & 3) * 2;       // d 0..127
#pragma unroll
            for (int half = 0; half < 2; half++) {
                int q = bx * 128 + m0 + mi * 16 + (lane >> 2) + half * 8;
                float d0 = acc[mi][ni][half * 2], d1 = acc[mi][ni][half * 2 + 1];
                size_t base = ((size_t)b * 1024 + q) * 1024 + h * 128 + cc;
                *(uint32_t*)(g_Oh + base) = pack2h(d0, d1);
            }
        }
}

// ---------------------------------------------------------------------------
// Final GEMM (HMMA): X = [dec | O] @ Wf + bf + dec  (K = 2048)
// dec-half (chunks 0..31): 3-term; O-half (chunks 32..63): 1-term.
// ---------------------------------------------------------------------------
__global__ __launch_bounds__(256, 1) void final_mma_kernel(
    const float* __restrict__ dec, const float* __restrict__ bf) {
    extern __shared__ char smem[];
    uint32_t sb = smem_to_u32(smem);
    int tid = threadIdx.x, lane = tid & 31, w = tid >> 5;
    int m0 = (w & 3) * 32, n0 = (w >> 2) * 64;
    int bx = blockIdx.x, by = blockIdx.y;
    const size_t arow0 = (size_t)by * 128;

    const __nv_bfloat16* Bh = g_Wft_h + (size_t)bx * 128 * 2048;
    const __nv_bfloat16* Bl = g_Wft_l + (size_t)bx * 128 * 2048;

    float acc[2][8][4];
    ACC_ZERO();

#define LOADC(cc, buf) do { \
    int _k0 = (cc) * 32; \
    if (_k0 < 1024) \
        load_chunk_t<3>((buf), g_dech + arow0*1024 + _k0, g_decl + arow0*1024 + _k0, \
                        Bh + _k0, Bl + _k0, 1024, 2048, tid); \
    else \
        load_chunk_t<1>((buf), g_Oh + arow0*1024 + (_k0 - 1024), nullptr, \
                        Bh + _k0, nullptr, 1024, 2048, tid); \
} while (0)
#define COMPUTEC(cc, buf) do { \
    if ((cc) < 32) compute_chunk_t<3>((buf), lane, m0, n0, acc); \
    else           compute_chunk_t<1>((buf), lane, m0, n0, acc); \
} while (0)
    PIPELINE3(64, LOADC, COMPUTEC);
#undef LOADC
#undef COMPUTEC

#pragma unroll
    for (int mi = 0; mi < 2; mi++)
#pragma unroll
        for (int ni = 0; ni < 8; ni++) {
            int cc = bx * 128 + n0 + ni * 8 + (lane & 3) * 2;
            float2 bv = *(const float2*)(bf + cc);
#pragma unroll
            for (int half = 0; half < 2; half++) {
                int rr = by * 128 + m0 + mi * 16 + (lane >> 2) + half * 8;
                float d0 = acc[mi][ni][half * 2], d1 = acc[mi][ni][half * 2 + 1];
                float2 dv = *(const float2*)(dec + (size_t)rr * 1024 + cc);
                *(float2*)(g_X + (size_t)rr * 1024 + cc) =
                    make_float2(d0 + bv.x + dv.x, d1 + bv.y + dv.y);
            }
        }
}

// ---------------------------------------------------------------------------
// LayerNorm
// ---------------------------------------------------------------------------
__global__ __launch_bounds__(256) void ln_kernel(
    const float* __restrict__ gamma, const float* __restrict__ beta,
    float* __restrict__ out) {
    const int rowid = blockIdx.x;
    const int tid = threadIdx.x;
    const float* rp = g_X + (size_t)rowid * 1024;

    float4 x = *(const float4*)(rp + tid * 4);
    __shared__ float red[256];
    red[tid] = x.x + x.y + x.z + x.w;
    __syncthreads();
#pragma unroll
    for (int s = 128; s > 0; s >>= 1) {
        if (tid < s) red[tid] += red[tid + s];
        __syncthreads();
    }
    float mean = red[0] * (1.0f / 1024.0f);
    __syncthreads();

    float d0 = x.x - mean, d1 = x.y - mean, d2 = x.z - mean, d3 = x.w - mean;
    red[tid] = d0 * d0 + d1 * d1 + d2 * d2 + d3 * d3;
    __syncthreads();
#pragma unroll
    for (int s = 128; s > 0; s >>= 1) {
        if (tid < s) red[tid] += red[tid + s];
        __syncthreads();
    }
    float var = red[0] * (1.0f / 1024.0f);
    float inv = rsqrtf(var + 1e-5f);

    float4 g = *(const float4*)(gamma + tid * 4);
    float4 bt = *(const float4*)(beta + tid * 4);
    float* optr = out + (size_t)rowid * 1024 + tid * 4;
    *(float4*)optr = make_float4(d0 * inv * g.x + bt.x,
                                 d1 * inv * g.y + bt.y,
                                 d2 * inv * g.z + bt.z,
                                 d3 * inv * g.w + bt.w);
}

// ---------------------------------------------------------------------------
extern "C" void kernel_launch(void* const* d_in, const int* in_sizes, int n_in,
                              void* d_out, int out_size) {
    (void)in_sizes; (void)n_in; (void)out_size;
    const float* mem   = (const float*)d_in[0];
    const float* dec   = (const float*)d_in[1];
    const float* qmask = (const float*)d_in[2];
    const float* Wk    = (const float*)d_in[3];
    const float* Wv    = (const float*)d_in[4];
    const float* Wq    = (const float*)d_in[5];
    const float* Wf    = (const float*)d_in[6];
    const float* bf    = (const float*)d_in[7];
    const float* gamma = (const float*)d_in[8];
    const float* beta  = (const float*)d_in[9];
    const void*  mask  = d_in[10];

    float* out  = (float*)d_out;
    float* attn = out + XSIZE;

    cudaFuncSetAttribute(projKQ_mma_kernel, cudaFuncAttributeMaxDynamicSharedMemorySize, SMEM_TOT);
    cudaFuncSetAttribute(projV_mma_kernel,  cudaFuncAttributeMaxDynamicSharedMemorySize, SMEM_TOT);
    cudaFuncSetAttribute(scores_mma_kernel, cudaFuncAttributeMaxDynamicSharedMemorySize, SMEM_TOT);
    cudaFuncSetAttribute(pv_mma_kernel,     cudaFuncAttributeMaxDynamicSharedMemorySize, SMEM_TOT);
    cudaFuncSetAttribute(final_mma_kernel,  cudaFuncAttributeMaxDynamicSharedMemorySize, SMEM_TOT);

    detect_mask_kernel<<<1, 32>>>(mask);
    conv_hilo_kernel<<<8192, 256>>>(mem, 0, XSIZE / 4);
    conv_hilo_kernel<<<8192, 256>>>(dec, 1, XSIZE / 4);
    convT_kernel<<<dim3(32, 32), dim3(32, 8)>>>(Wk, 0, 1024, 1024);
    convT_kernel<<<dim3(32, 32), dim3(32, 8)>>>(Wv, 1, 1024, 1024);
    convT_kernel<<<dim3(32, 32), dim3(32, 8)>>>(Wq, 2, 1024, 1024);
    convT_kernel<<<dim3(32, 64), dim3(32, 8)>>>(Wf, 3, 2048, 1024);

    projKQ_mma_kernel<<<dim3(8, 64, 2), 256, SMEM_TOT>>>();
    projV_mma_kernel<<<dim3(8, 64), 256, SMEM_TOT>>>();
    transposeV_kernel<<<dim3(4, 32, 64), dim3(32, 8)>>>();
    scores_mma_kernel<<<dim3(8, 8, 64), 256, SMEM_TOT>>>(attn);
    softmax_kernel<<<65536, 256>>>(attn, qmask, mask);
    pv_mma_kernel<<<dim3(8, 64), 256, SMEM_TOT>>>();
    final_mma_kernel<<<dim3(8, 64), 256, SMEM_TOT>>>(dec, bf);
    ln_kernel<<<8192, 256>>>(gamma, beta, out);
}

// round 8
// speedup vs baseline: 2.6588x; 1.0186x over previous
#include <cuda_runtime.h>
#include <cuda_bf16.h>
#include <cstdint>
#include <math.h>

// ---------------------------------------------------------------------------
// Problem constants
// ---------------------------------------------------------------------------
#define NB 8
#define SQ 1024
#define SK 1024
#define DD 1024
#define NH 8
#define DH 128
#define HB (NH*NB)              // 64
#define XSIZE (NB*SQ*DD)        // 8388608
#define NEGV (-4294967295.0f)
#define SCALE 0.0883883476483184405f

// mma GEMM smem: per buffer operand slots, each 128 rows x 32 bf16,
// row stride 80B (64B data + 16B skew). 3-stage pipeline.
#define ROWB 80
#define OP_BYTES (128*ROWB)       // 10240
#define OFF_AL (1*OP_BYTES)
#define OFF_BL (3*OP_BYTES)
#define BUF_BYTES (4*OP_BYTES)    // 40960  (3-term: Ah,Al,Bh,Bl)
#define BUF1_BYTES (2*OP_BYTES)   // 20480  (1-term: Ah,Bh)
#define SMEM_TOT (3*BUF_BYTES)    // 122880
#define SMEM1_TOT (3*BUF1_BYTES)  // 61440

// attn_fused smem layout
#define ROWQ 272                  // 256B data + 16B skew
#define S_PITCH 1032              // fp32 words per S row (skewed)
#define SM_Q (32*S_PITCH*4)       // 132096: Q region starts after S
#define B_HL (64*ROWQ)            // 17408
#define B_BUF (2*B_HL)            // 34816
#define SM_B (SM_Q + 2*32*ROWQ)   // 132096 + 17408 = 149504
#define SMEM_ATTN (SM_B + 2*B_BUF) // 219136

// ---------------------------------------------------------------------------
// Scratch (device globals — referenced ONLY from device code)
// ---------------------------------------------------------------------------
__device__ __nv_bfloat16 g_memh[NB*SK*DD], g_meml[NB*SK*DD];
__device__ __nv_bfloat16 g_dech[NB*SQ*DD], g_decl[NB*SQ*DD];
__device__ __nv_bfloat16 g_Wkt_h[DD*DD], g_Wkt_l[DD*DD];
__device__ __nv_bfloat16 g_Wvt_h[DD*DD];
__device__ __nv_bfloat16 g_Wqt_h[DD*DD], g_Wqt_l[DD*DD];
__device__ __nv_bfloat16 g_Wft_h[DD*2*DD], g_Wft_l[DD*2*DD];
__device__ __nv_bfloat16 g_Kh[HB*SK*DH], g_Kl[HB*SK*DH];
__device__ __nv_bfloat16 g_Qh[HB*SQ*DH], g_Ql[HB*SQ*DH];
__device__ float         g_V[HB*SK*DH];
__device__ __nv_bfloat16 g_Vth[HB*DH*SK];
__device__ __nv_bfloat16 g_Ph[(size_t)HB*SQ*SK];
__device__ __nv_bfloat16 g_Oh[NB*SQ*DD];
__device__ float         g_X[NB*SQ*DD];
__device__ int           g_maskmode;

// ---------------------------------------------------------------------------
// Helpers
// ---------------------------------------------------------------------------
__device__ __forceinline__ uint32_t smem_to_u32(const void* p) {
    uint32_t a;
    asm("{ .reg .u64 t; cvta.to.shared.u64 t, %1; cvt.u32.u64 %0, t; }" : "=r"(a) : "l"(p));
    return a;
}

__device__ __forceinline__ void cp16(uint32_t dst, const void* src) {
    asm volatile("cp.async.cg.shared.global [%0], [%1], 16;" :: "r"(dst), "l"(src));
}
#define CP_COMMIT() asm volatile("cp.async.commit_group;" ::: "memory")
#define CP_WAIT(n)  asm volatile("cp.async.wait_group %0;" :: "n"(n) : "memory")

__device__ __forceinline__ void ldm_x4(uint32_t* r, uint32_t addr) {
    asm volatile("ldmatrix.sync.aligned.m8n8.x4.shared.b16 {%0,%1,%2,%3}, [%4];"
        : "=r"(r[0]), "=r"(r[1]), "=r"(r[2]), "=r"(r[3]) : "r"(addr));
}

__device__ __forceinline__ void mma16816(float* d, const uint32_t* a, const uint32_t* b) {
    asm volatile("mma.sync.aligned.m16n8k16.row.col.f32.bf16.bf16.f32 "
        "{%0,%1,%2,%3}, {%4,%5,%6,%7}, {%8,%9}, {%0,%1,%2,%3};"
        : "+f"(d[0]), "+f"(d[1]), "+f"(d[2]), "+f"(d[3])
        : "r"(a[0]), "r"(a[1]), "r"(a[2]), "r"(a[3]), "r"(b[0]), "r"(b[1]));
}

__device__ __forceinline__ void split_hilo(float v, __nv_bfloat16& h, __nv_bfloat16& l) {
    h = __float2bfloat16(v);
    l = __float2bfloat16(v - __bfloat162float(h));
}
__device__ __forceinline__ uint32_t pack2h(float v0, float v1) {
    __nv_bfloat16 h0, l0, h1, l1;
    split_hilo(v0, h0, l0); split_hilo(v1, h1, l1);
    __nv_bfloat162 p = __halves2bfloat162(h0, h1);
    return *reinterpret_cast<uint32_t*>(&p);
}
__device__ __forceinline__ uint32_t pack2l(float v0, float v1) {
    __nv_bfloat16 h0, l0, h1, l1;
    split_hilo(v0, h0, l0); split_hilo(v1, h1, l1);
    __nv_bfloat162 p = __halves2bfloat162(l0, l1);
    return *reinterpret_cast<uint32_t*>(&p);
}

// ---------------------------------------------------------------------------
// mma GEMM building blocks. TERMS=3: hi/lo split; TERMS=1: single bf16,
// compact 2-slot buffer (B at OP_BYTES).
// ---------------------------------------------------------------------------
template<int TERMS>
__device__ __forceinline__ void load_chunk_t(
    uint32_t sbuf,
    const __nv_bfloat16* __restrict__ Ah, const __nv_bfloat16* __restrict__ Al,
    const __nv_bfloat16* __restrict__ Bh, const __nv_bfloat16* __restrict__ Bl,
    int lda, int ldb, int tid)
{
    constexpr uint32_t OFFB = (TERMS == 3) ? (uint32_t)(2*OP_BYTES) : (uint32_t)OP_BYTES;
#pragma unroll
    for (int i = tid; i < 512; i += 256) {
        int row = i >> 2, ch = i & 3;
        uint32_t d = sbuf + row*ROWB + ch*16;
        size_t ao = (size_t)row * lda * 2 + ch*16;
        size_t bo = (size_t)row * ldb * 2 + ch*16;
        cp16(d,        (const char*)Ah + ao);
        cp16(d + OFFB, (const char*)Bh + bo);
        if (TERMS == 3) {
            cp16(d + OFF_AL, (const char*)Al + ao);
            cp16(d + OFF_BL, (const char*)Bl + bo);
        }
    }
}

template<int TERMS>
__device__ __forceinline__ void compute_chunk_t(uint32_t sbuf, int lane, int m0, int n0,
                                                float acc[2][8][4])
{
    constexpr uint32_t OFFB = (TERMS == 3) ? (uint32_t)(2*OP_BYTES) : (uint32_t)OP_BYTES;
#pragma unroll
    for (int kk = 0; kk < 2; kk++) {
        uint32_t ah[2][4], al[2][4];
        int arow = m0 + (lane & 15);
        uint32_t abase = sbuf + kk*32 + ((lane >> 4) & 1)*16;
        ldm_x4(ah[0], abase + arow*ROWB);
        ldm_x4(ah[1], abase + (arow + 16)*ROWB);
        if (TERMS == 3) {
            ldm_x4(al[0], abase + OFF_AL + arow*ROWB);
            ldm_x4(al[1], abase + OFF_AL + (arow + 16)*ROWB);
        }

        uint32_t bh[4][4], bl[4][4];
        int brow = n0 + ((lane >> 4) << 3) + (lane & 7);
        uint32_t bko = ((lane >> 3) & 1) * 16 + kk*32;
#pragma unroll
        for (int nb = 0; nb < 4; nb++) {
            ldm_x4(bh[nb], sbuf + OFFB + (brow + nb*16)*ROWB + bko);
            if (TERMS == 3)
                ldm_x4(bl[nb], sbuf + OFF_BL + (brow + nb*16)*ROWB + bko);
        }
#pragma unroll
        for (int mi = 0; mi < 2; mi++)
#pragma unroll
            for (int ni = 0; ni < 8; ni++) {
                const uint32_t* BH = &bh[ni >> 1][(ni & 1) * 2];
                mma16816(acc[mi][ni], ah[mi], BH);
                if (TERMS == 3) {
                    const uint32_t* BL = &bl[ni >> 1][(ni & 1) * 2];
                    mma16816(acc[mi][ni], al[mi], BH);
                    mma16816(acc[mi][ni], ah[mi], BL);
                }
            }
    }
}

#define ACC_ZERO() do { \
    _Pragma("unroll") for (int _i = 0; _i < 2; _i++) \
    _Pragma("unroll") for (int _j = 0; _j < 8; _j++) \
    _Pragma("unroll") for (int _k = 0; _k < 4; _k++) acc[_i][_j][_k] = 0.f; \
} while (0)

// 3-stage pipeline driver
#define PIPELINE3(KC, BUFSZ, LOADC, COMPUTEC) do { \
    { LOADC(0, sb + 0*(BUFSZ)); } CP_COMMIT(); \
    { LOADC(1, sb + 1*(BUFSZ)); } CP_COMMIT(); \
    for (int c = 0; c < (KC); c++) { \
        if (c + 2 < (KC)) { LOADC((c + 2), sb + ((c + 2) % 3)*(BUFSZ)); } \
        CP_COMMIT(); \
        CP_WAIT(2); \
        __syncthreads(); \
        { COMPUTEC(c, sb + (c % 3)*(BUFSZ)); } \
        __syncthreads(); \
    } \
} while (0)

// ---------------------------------------------------------------------------
// Mask dtype detection
// ---------------------------------------------------------------------------
__global__ void detect_mask_kernel(const void* __restrict__ mask) {
    int t = threadIdx.x;
    const int* pi = (const int*)mask;
    const float* pf = (const float*)mask;
    bool oki = true, okf = true;
    for (int i = t; i < 256; i += 32) {
        int v = pi[i];
        oki = oki && (v == 0 || v == 1);
        float f = pf[i];
        okf = okf && (f == 0.0f || f == 1.0f);
    }
    oki = __all_sync(0xFFFFFFFFu, oki);
    okf = __all_sync(0xFFFFFFFFu, okf);
    if (t == 0) g_maskmode = oki ? 0 : (okf ? 1 : 2);
}

// ---------------------------------------------------------------------------
// fp32 -> bf16 hi/lo. which=0 -> g_mem*, which=1 -> g_dec*
// ---------------------------------------------------------------------------
__global__ void conv_hilo_kernel(const float* __restrict__ src, int which, int n4) {
    __nv_bfloat16* __restrict__ dh = which ? g_dech : g_memh;
    __nv_bfloat16* __restrict__ dl = which ? g_decl : g_meml;
    int idx = blockIdx.x * blockDim.x + threadIdx.x;
    if (idx >= n4) return;
    float4 v = ((const float4*)src)[idx];
    uint2 hw, lw;
    hw.x = pack2h(v.x, v.y); hw.y = pack2h(v.z, v.w);
    lw.x = pack2l(v.x, v.y); lw.y = pack2l(v.z, v.w);
    ((uint2*)dh)[idx] = hw;
    ((uint2*)dl)[idx] = lw;
}

// ---------------------------------------------------------------------------
// W [K][N] fp32 -> Wt [N][K] bf16 hi/lo. which: 0=Wk 1=Wv(hi only) 2=Wq 3=Wf
// ---------------------------------------------------------------------------
__global__ void convT_kernel(const float* __restrict__ src, int which, int K, int N) {
    __nv_bfloat16 *dh, *dl;
    if (which == 0)      { dh = g_Wkt_h; dl = g_Wkt_l; }
    else if (which == 1) { dh = g_Wvt_h; dl = nullptr; }
    else if (which == 2) { dh = g_Wqt_h; dl = g_Wqt_l; }
    else                 { dh = g_Wft_h; dl = g_Wft_l; }

    __shared__ float t[32][33];
    int n0 = blockIdx.x * 32, k0 = blockIdx.y * 32;
    int tx = threadIdx.x;
    for (int i = threadIdx.y; i < 32; i += 8)
        t[i][tx] = src[(size_t)(k0 + i) * N + n0 + tx];
    __syncthreads();
    for (int i = threadIdx.y; i < 32; i += 8) {
        float v = t[tx][i];
        __nv_bfloat16 h, l;
        split_hilo(v, h, l);
        size_t o = (size_t)(n0 + i) * K + k0 + tx;
        dh[o] = h;
        if (dl) dl[o] = l;
    }
}

// ---------------------------------------------------------------------------
// V [hb][1024][128] fp32 -> Vt [hb][128][1024] bf16 (hi only)
// ---------------------------------------------------------------------------
__global__ void transposeV_kernel() {
    __shared__ float t[32][33];
    int hb = blockIdx.z;
    int d0 = blockIdx.x * 32, s0 = blockIdx.y * 32;
    int tx = threadIdx.x;
    const float* src = g_V + (size_t)hb * SK * DH;
    for (int i = threadIdx.y; i < 32; i += 8)
        t[i][tx] = src[(size_t)(s0 + i) * 128 + d0 + tx];
    __syncthreads();
    for (int i = threadIdx.y; i < 32; i += 8) {
        size_t o = (size_t)hb * DH * SK + (size_t)(d0 + i) * 1024 + s0 + tx;
        g_Vth[o] = __float2bfloat16(t[tx][i]);
    }
}

// ---------------------------------------------------------------------------
// Projection GEMM K/Q (HMMA, 3-term): z=0 K, z=1 Q. Head-split bf16 hi/lo out.
// ---------------------------------------------------------------------------
__global__ __launch_bounds__(256, 1) void projKQ_mma_kernel() {
    extern __shared__ char smem[];
    uint32_t sb = smem_to_u32(smem);
    int tid = threadIdx.x, lane = tid & 31, w = tid >> 5;
    int m0 = (w & 3) * 32, n0 = (w >> 2) * 64;
    int bx = blockIdx.x, by = blockIdx.y, z = blockIdx.z;

    const __nv_bfloat16* Ah = ((z == 1) ? g_dech : g_memh) + (size_t)by * 128 * 1024;
    const __nv_bfloat16* Al = ((z == 1) ? g_decl : g_meml) + (size_t)by * 128 * 1024;
    const __nv_bfloat16* Bh = ((z == 0) ? g_Wkt_h : g_Wqt_h) + (size_t)bx * 128 * 1024;
    const __nv_bfloat16* Bl = ((z == 0) ? g_Wkt_l : g_Wqt_l) + (size_t)bx * 128 * 1024;

    float acc[2][8][4];
    ACC_ZERO();

#define LOADC(cc, buf) load_chunk_t<3>((buf), Ah + (cc)*32, Al + (cc)*32, Bh + (cc)*32, Bl + (cc)*32, 1024, 1024, tid)
#define COMPUTEC(cc, buf) compute_chunk_t<3>((buf), lane, m0, n0, acc)
    PIPELINE3(32, BUF_BYTES, LOADC, COMPUTEC);
#undef LOADC
#undef COMPUTEC

#pragma unroll
    for (int mi = 0; mi < 2; mi++)
#pragma unroll
        for (int ni = 0; ni < 8; ni++) {
            int cc = n0 + ni * 8 + (lane & 3) * 2;
#pragma unroll
            for (int half = 0; half < 2; half++) {
                int rr = by * 128 + m0 + mi * 16 + (lane >> 2) + half * 8;
                float d0 = acc[mi][ni][half * 2], d1 = acc[mi][ni][half * 2 + 1];
                int bb = rr >> 10, ss = rr & 1023;
                size_t base = (((size_t)(bx * 8 + bb)) * 1024 + ss) * 128 + cc;
                __nv_bfloat16* oh = (z == 0) ? g_Kh : g_Qh;
                __nv_bfloat16* ol = (z == 0) ? g_Kl : g_Ql;
                *(uint32_t*)(oh + base) = pack2h(d0, d1);
                *(uint32_t*)(ol + base) = pack2l(d0, d1);
            }
        }
}

// ---------------------------------------------------------------------------
// Projection GEMM V (HMMA, 1-term, compact smem): fp32 head-split out
// ---------------------------------------------------------------------------
__global__ __launch_bounds__(256, 2) void projV_mma_kernel() {
    extern __shared__ char smem[];
    uint32_t sb = smem_to_u32(smem);
    int tid = threadIdx.x, lane = tid & 31, w = tid >> 5;
    int m0 = (w & 3) * 32, n0 = (w >> 2) * 64;
    int bx = blockIdx.x, by = blockIdx.y;

    const __nv_bfloat16* Ah = g_memh + (size_t)by * 128 * 1024;
    const __nv_bfloat16* Bh = g_Wvt_h + (size_t)bx * 128 * 1024;

    float acc[2][8][4];
    ACC_ZERO();

#define LOADC(cc, buf) load_chunk_t<1>((buf), Ah + (cc)*32, nullptr, Bh + (cc)*32, nullptr, 1024, 1024, tid)
#define COMPUTEC(cc, buf) compute_chunk_t<1>((buf), lane, m0, n0, acc)
    PIPELINE3(32, BUF1_BYTES, LOADC, COMPUTEC);
#undef LOADC
#undef COMPUTEC

#pragma unroll
    for (int mi = 0; mi < 2; mi++)
#pragma unroll
        for (int ni = 0; ni < 8; ni++) {
            int cc = n0 + ni * 8 + (lane & 3) * 2;
#pragma unroll
            for (int half = 0; half < 2; half++) {
                int rr = by * 128 + m0 + mi * 16 + (lane >> 2) + half * 8;
                float d0 = acc[mi][ni][half * 2], d1 = acc[mi][ni][half * 2 + 1];
                int bb = rr >> 10, ss = rr & 1023;
                size_t base = (((size_t)(bx * 8 + bb)) * 1024 + ss) * 128 + cc;
                *(float2*)(g_V + base) = make_float2(d0, d1);
            }
        }
}

// ---------------------------------------------------------------------------
// FUSED scores+softmax: one CTA = 32 query rows x 1024 keys for one hb.
// S lives in smem; writes P fp32 (attns output) + Ph bf16 directly.
// ---------------------------------------------------------------------------
__global__ __launch_bounds__(256, 1) void attn_fused_kernel(
    float* __restrict__ attn, const float* __restrict__ qmask,
    const void* __restrict__ mask)
{
    extern __shared__ char smem[];
    uint32_t sb = smem_to_u32(smem);
    float* Ss = (float*)smem;
    int tid = threadIdx.x, lane = tid & 31, w = tid >> 5;
    const int wm = w >> 2;      // 0..1 -> m16 slice
    const int wn = w & 3;       // 0..3 -> n16 slice within 64-key tile
    int blk = blockIdx.x;       // 0..31 row block
    int y = blockIdx.y;         // 0..63 ; b-major for mask L2 reuse
    int h = y & 7, b = y >> 3;
    int hb = h * 8 + b;
    int q0 = blk * 32;

    const char* Qh = (const char*)(g_Qh + ((size_t)hb * 1024 + q0) * 128);
    const char* Ql = (const char*)(g_Ql + ((size_t)hb * 1024 + q0) * 128);
    const char* Kh = (const char*)(g_Kh + (size_t)hb * 1024 * 128);
    const char* Kl = (const char*)(g_Kl + (size_t)hb * 1024 * 128);

    // ---- load Q (32 rows x 256B, hi+lo) ----
#pragma unroll
    for (int i = tid; i < 512; i += 256) {
        int row = i >> 4, ch = i & 15;
        uint32_t d = sb + SM_Q + row * ROWQ + ch * 16;
        size_t o = (size_t)row * 256 + ch * 16;
        cp16(d, Qh + o);
        cp16(d + 32 * ROWQ, Ql + o);
    }
    CP_COMMIT();

    // ---- preload K tiles 0,1 (64 keys x 256B, hi+lo each) ----
#pragma unroll
    for (int t = 0; t < 2; t++) {
        uint32_t bbuf = sb + SM_B + t * B_BUF;
#pragma unroll
        for (int i = tid; i < 1024; i += 256) {
            int row = i >> 4, ch = i & 15;
            uint32_t d = bbuf + row * ROWQ + ch * 16;
            size_t o = (size_t)t * 64 * 256 + (size_t)row * 256 + ch * 16;
            cp16(d, Kh + o);
            cp16(d + B_HL, Kl + o);
        }
        CP_COMMIT();
    }

    // ---- Q ready: hoist A fragments for all 8 kk steps ----
    CP_WAIT(2);
    __syncthreads();
    uint32_t ah_reg[8][4], al_reg[8][4];
    {
        uint32_t abase = sb + SM_Q + (uint32_t)(wm * 16 + (lane & 15)) * ROWQ
                         + ((lane >> 4) & 1) * 16;
#pragma unroll
        for (int kk = 0; kk < 8; kk++) {
            ldm_x4(ah_reg[kk], abase + kk * 32);
            ldm_x4(al_reg[kk], abase + 32 * ROWQ + kk * 32);
        }
    }

    // ---- stream 16 K tiles of 64 keys, double-buffered ----
    const int gid = lane >> 2, tig = lane & 3;
    for (int t = 0; t < 16; t++) {
        CP_WAIT(1);
        __syncthreads();
        uint32_t bbuf = sb + SM_B + (t & 1) * B_BUF;
        float acc[2][4];
#pragma unroll
        for (int ni = 0; ni < 2; ni++)
#pragma unroll
            for (int k = 0; k < 4; k++) acc[ni][k] = 0.f;

        uint32_t bbase = bbuf + (uint32_t)(wn * 16 + ((lane >> 4) << 3) + (lane & 7)) * ROWQ
                         + ((lane >> 3) & 1) * 16;
#pragma unroll
        for (int kk = 0; kk < 8; kk++) {
            uint32_t bh[4], bl[4];
            ldm_x4(bh, bbase + kk * 32);
            ldm_x4(bl, bbase + B_HL + kk * 32);
#pragma unroll
            for (int ni = 0; ni < 2; ni++) {
                mma16816(acc[ni], ah_reg[kk], &bh[ni * 2]);
                mma16816(acc[ni], al_reg[kk], &bh[ni * 2]);
                mma16816(acc[ni], ah_reg[kk], &bl[ni * 2]);
            }
        }
        // write S tile to smem (scaled)
        int col0 = t * 64 + wn * 16;
#pragma unroll
        for (int ni = 0; ni < 2; ni++)
#pragma unroll
            for (int half = 0; half < 2; half++) {
                int row = wm * 16 + gid + half * 8;
                int col = col0 + ni * 8 + tig * 2;
                *(float2*)(Ss + row * S_PITCH + col) =
                    make_float2(acc[ni][half * 2] * SCALE, acc[ni][half * 2 + 1] * SCALE);
            }
        __syncthreads();
        if (t + 2 < 16) {
            uint32_t nbuf = sb + SM_B + (t & 1) * B_BUF;
#pragma unroll
            for (int i = tid; i < 1024; i += 256) {
                int row = i >> 4, ch = i & 15;
                uint32_t d = nbuf + row * ROWQ + ch * 16;
                size_t o = (size_t)(t + 2) * 64 * 256 + (size_t)row * 256 + ch * 16;
                cp16(d, Kh + o);
                cp16(d + B_HL, Kl + o);
            }
        }
        CP_COMMIT();
    }
    __syncthreads();

    // ---- softmax phase: warp w handles rows w*4 .. w*4+3 ----
    const int mode = g_maskmode;
#pragma unroll 1
    for (int j = 0; j < 4; j++) {
        int r = w * 4 + j;
        int q = q0 + r;
        const float* srow = Ss + r * S_PITCH;
        const size_t mrow = ((size_t)b * 1024 + q) * 1024;

        float v[32];
        float mx = -3.4e38f;
#pragma unroll
        for (int c8 = 0; c8 < 8; c8++) {
            int col = c8 * 128 + lane * 4;
            float4 x = *(const float4*)(srow + col);
            int m0i, m1i, m2i, m3i;
            if (mode == 0) {
                int4 mv = *(const int4*)((const int*)mask + mrow + col);
                m0i = mv.x; m1i = mv.y; m2i = mv.z; m3i = mv.w;
            } else if (mode == 1) {
                float4 mv = *(const float4*)((const float*)mask + mrow + col);
                m0i = (mv.x != 0.f); m1i = (mv.y != 0.f); m2i = (mv.z != 0.f); m3i = (mv.w != 0.f);
            } else {
                uchar4 mv = *(const uchar4*)((const unsigned char*)mask + mrow + col);
                m0i = mv.x; m1i = mv.y; m2i = mv.z; m3i = mv.w;
            }
            v[c8*4+0] = m0i ? NEGV : x.x;
            v[c8*4+1] = m1i ? NEGV : x.y;
            v[c8*4+2] = m2i ? NEGV : x.z;
            v[c8*4+3] = m3i ? NEGV : x.w;
            mx = fmaxf(mx, fmaxf(fmaxf(v[c8*4+0], v[c8*4+1]), fmaxf(v[c8*4+2], v[c8*4+3])));
        }
#pragma unroll
        for (int s = 16; s > 0; s >>= 1)
            mx = fmaxf(mx, __shfl_xor_sync(0xFFFFFFFFu, mx, s));

        float sum = 0.f;
#pragma unroll
        for (int i = 0; i < 32; i++) {
            v[i] = expf(v[i] - mx);
            sum += v[i];
        }
#pragma unroll
        for (int s = 16; s > 0; s >>= 1)
            sum += __shfl_xor_sync(0xFFFFFFFFu, sum, s);

        float inv = qmask[b * 1024 + q] / sum;
        float* prow = attn + ((size_t)hb * 1024 + q) * 1024;
        __nv_bfloat16* phrow = g_Ph + ((size_t)hb * 1024 + q) * 1024;
#pragma unroll
        for (int c8 = 0; c8 < 8; c8++) {
            int col = c8 * 128 + lane * 4;
            float p0 = v[c8*4+0] * inv, p1 = v[c8*4+1] * inv;
            float p2 = v[c8*4+2] * inv, p3 = v[c8*4+3] * inv;
            *(float4*)(prow + col) = make_float4(p0, p1, p2, p3);
            uint2 hw;
            hw.x = pack2h(p0, p1); hw.y = pack2h(p2, p3);
            *(uint2*)(phrow + col) = hw;
        }
    }
}

// ---------------------------------------------------------------------------
// PV GEMM (HMMA, 1-term, compact smem): O = P @ V ; bf16 out
// ---------------------------------------------------------------------------
__global__ __launch_bounds__(256, 2) void pv_mma_kernel() {
    extern __shared__ char smem[];
    uint32_t sb = smem_to_u32(smem);
    int tid = threadIdx.x, lane = tid & 31, w = tid >> 5;
    int m0 = (w & 3) * 32, n0 = (w >> 2) * 64;
    int bx = blockIdx.x, hb = blockIdx.y;

    const __nv_bfloat16* Ah = g_Ph + ((size_t)hb * 1024 + bx * 128) * 1024;
    const __nv_bfloat16* Bh = g_Vth + (size_t)hb * DH * SK;

    float acc[2][8][4];
    ACC_ZERO();

#define LOADC(cc, buf) load_chunk_t<1>((buf), Ah + (cc)*32, nullptr, Bh + (cc)*32, nullptr, 1024, 1024, tid)
#define COMPUTEC(cc, buf) compute_chunk_t<1>((buf), lane, m0, n0, acc)
    PIPELINE3(32, BUF1_BYTES, LOADC, COMPUTEC);
#undef LOADC
#undef COMPUTEC

    const int b = hb & 7, h = hb >> 3;
#pragma unroll
    for (int mi = 0; mi < 2; mi++)
#pragma unroll
        for (int ni = 0; ni < 8; ni++) {
            int cc = n0 + ni * 8 + (lane & 3) * 2;
#pragma unroll
            for (int half = 0; half < 2; half++) {
                int q = bx * 128 + m0 + mi * 16 + (lane >> 2) + half * 8;
                float d0 = acc[mi][ni][half * 2], d1 = acc[mi][ni][half * 2 + 1];
                size_t base = ((size_t)b * 1024 + q) * 1024 + h * 128 + cc;
                *(uint32_t*)(g_Oh + base) = pack2h(d0, d1);
            }
        }
}

// ---------------------------------------------------------------------------
// Final GEMM (HMMA): X = [dec | O] @ Wf + bf + dec  (K = 2048)
// dec-half 3-term; O-half 1-term. 4-slot buffers throughout.
// ---------------------------------------------------------------------------
__global__ __launch_bounds__(256, 1) void final_mma_kernel(
    const float* __restrict__ dec, const float* __restrict__ bf) {
    extern __shared__ char smem[];
    uint32_t sb = smem_to_u32(smem);
    int tid = threadIdx.x, lane = tid & 31, w = tid >> 5;
    int m0 = (w & 3) * 32, n0 = (w >> 2) * 64;
    int bx = blockIdx.x, by = blockIdx.y;
    const size_t arow0 = (size_t)by * 128;

    const __nv_bfloat16* Bh = g_Wft_h + (size_t)bx * 128 * 2048;
    const __nv_bfloat16* Bl = g_Wft_l + (size_t)bx * 128 * 2048;

    float acc[2][8][4];
    ACC_ZERO();

#define LOADC(cc, buf) do { \
    int _k0 = (cc) * 32; \
    if (_k0 < 1024) \
        load_chunk_t<3>((buf), g_dech + arow0*1024 + _k0, g_decl + arow0*1024 + _k0, \
                        Bh + _k0, Bl + _k0, 1024, 2048, tid); \
    else \
        load_chunk_t<1>((buf), g_Oh + arow0*1024 + (_k0 - 1024), nullptr, \
                        Bh + _k0, nullptr, 1024, 2048, tid); \
} while (0)
#define COMPUTEC(cc, buf) do { \
    if ((cc) < 32) compute_chunk_t<3>((buf), lane, m0, n0, acc); \
    else           compute_chunk_t<1>((buf), lane, m0, n0, acc); \
} while (0)
    PIPELINE3(64, BUF_BYTES, LOADC, COMPUTEC);
#undef LOADC
#undef COMPUTEC

#pragma unroll
    for (int mi = 0; mi < 2; mi++)
#pragma unroll
        for (int ni = 0; ni < 8; ni++) {
            int cc = bx * 128 + n0 + ni * 8 + (lane & 3) * 2;
            float2 bv = *(const float2*)(bf + cc);
#pragma unroll
            for (int half = 0; half < 2; half++) {
                int rr = by * 128 + m0 + mi * 16 + (lane >> 2) + half * 8;
                float d0 = acc[mi][ni][half * 2], d1 = acc[mi][ni][half * 2 + 1];
                float2 dv = *(const float2*)(dec + (size_t)rr * 1024 + cc);
                *(float2*)(g_X + (size_t)rr * 1024 + cc) =
                    make_float2(d0 + bv.x + dv.x, d1 + bv.y + dv.y);
            }
        }
}

// ---------------------------------------------------------------------------
// LayerNorm
// ---------------------------------------------------------------------------
__global__ __launch_bounds__(256) void ln_kernel(
    const float* __restrict__ gamma, const float* __restrict__ beta,
    float* __restrict__ out) {
    const int rowid = blockIdx.x;
    const int tid = threadIdx.x;
    const float* rp = g_X + (size_t)rowid * 1024;

    float4 x = *(const float4*)(rp + tid * 4);
    __shared__ float red[256];
    red[tid] = x.x + x.y + x.z + x.w;
    __syncthreads();
#pragma unroll
    for (int s = 128; s > 0; s >>= 1) {
        if (tid < s) red[tid] += red[tid + s];
        __syncthreads();
    }
    float mean = red[0] * (1.0f / 1024.0f);
    __syncthreads();

    float d0 = x.x - mean, d1 = x.y - mean, d2 = x.z - mean, d3 = x.w - mean;
    red[tid] = d0 * d0 + d1 * d1 + d2 * d2 + d3 * d3;
    __syncthreads();
#pragma unroll
    for (int s = 128; s > 0; s >>= 1) {
        if (tid < s) red[tid] += red[tid + s];
        __syncthreads();
    }
    float var = red[0] * (1.0f / 1024.0f);
    float inv = rsqrtf(var + 1e-5f);

    float4 g = *(const float4*)(gamma + tid * 4);
    float4 bt = *(const float4*)(beta + tid * 4);
    float* optr = out + (size_t)rowid * 1024 + tid * 4;
    *(float4*)optr = make_float4(d0 * inv * g.x + bt.x,
                                 d1 * inv * g.y + bt.y,
                                 d2 * inv * g.z + bt.z,
                                 d3 * inv * g.w + bt.w);
}

// ---------------------------------------------------------------------------
extern "C" void kernel_launch(void* const* d_in, const int* in_sizes, int n_in,
                              void* d_out, int out_size) {
    (void)in_sizes; (void)n_in; (void)out_size;
    const float* mem   = (const float*)d_in[0];
    const float* dec   = (const float*)d_in[1];
    const float* qmask = (const float*)d_in[2];
    const float* Wk    = (const float*)d_in[3];
    const float* Wv    = (const float*)d_in[4];
    const float* Wq    = (const float*)d_in[5];
    const float* Wf    = (const float*)d_in[6];
    const float* bf    = (const float*)d_in[7];
    const float* gamma = (const float*)d_in[8];
    const float* beta  = (const float*)d_in[9];
    const void*  mask  = d_in[10];

    float* out  = (float*)d_out;
    float* attn = out + XSIZE;

    cudaFuncSetAttribute(projKQ_mma_kernel, cudaFuncAttributeMaxDynamicSharedMemorySize, SMEM_TOT);
    cudaFuncSetAttribute(projV_mma_kernel,  cudaFuncAttributeMaxDynamicSharedMemorySize, SMEM1_TOT);
    cudaFuncSetAttribute(attn_fused_kernel, cudaFuncAttributeMaxDynamicSharedMemorySize, SMEM_ATTN);
    cudaFuncSetAttribute(pv_mma_kernel,     cudaFuncAttributeMaxDynamicSharedMemorySize, SMEM1_TOT);
    cudaFuncSetAttribute(final_mma_kernel,  cudaFuncAttributeMaxDynamicSharedMemorySize, SMEM_TOT);

    detect_mask_kernel<<<1, 32>>>(mask);
    conv_hilo_kernel<<<8192, 256>>>(mem, 0, XSIZE / 4);
    conv_hilo_kernel<<<8192, 256>>>(dec, 1, XSIZE / 4);
    convT_kernel<<<dim3(32, 32), dim3(32, 8)>>>(Wk, 0, 1024, 1024);
    convT_kernel<<<dim3(32, 32), dim3(32, 8)>>>(Wv, 1, 1024, 1024);
    convT_kernel<<<dim3(32, 32), dim3(32, 8)>>>(Wq, 2, 1024, 1024);
    convT_kernel<<<dim3(32, 64), dim3(32, 8)>>>(Wf, 3, 2048, 1024);

    projKQ_mma_kernel<<<dim3(8, 64, 2), 256, SMEM_TOT>>>();
    projV_mma_kernel<<<dim3(8, 64), 256, SMEM1_TOT>>>();
    transposeV_kernel<<<dim3(4, 32, 64), dim3(32, 8)>>>();
    attn_fused_kernel<<<dim3(32, 64), 256, SMEM_ATTN>>>(attn, qmask, mask);
    pv_mma_kernel<<<dim3(8, 64), 256, SMEM1_TOT>>>();
    final_mma_kernel<<<dim3(8, 64), 256, SMEM_TOT>>>(dec, bf);
    ln_kernel<<<8192, 256>>>(gamma, beta, out);
}